// round 5
// baseline (speedup 1.0000x reference)
#include <cuda_runtime.h>
#include <cstdint>
#include <math.h>

// ---------------- constants ----------------
#define DM 2048
#define NH 16
#define HD 128
#define LORA 512
#define SEQ 2048
#define BATCH 2
#define ROWS (BATCH*SEQ)   // 4096

// ---------------- scratch ----------------
__device__ float g_xc[ROWS * DM];
__device__ float g_kvlat[ROWS * LORA];
__device__ float g_k[ROWS * DM];
__device__ float g_v[ROWS * DM];
__device__ float g_q[ROWS * DM];
__device__ float g_vT[BATCH * NH * HD * SEQ];
__device__ float g_attn[ROWS * DM];
__device__ float g_wkvcT[LORA * DM];
__device__ float g_wkT[DM * LORA];
__device__ float g_wvT[DM * LORA];
__device__ float g_wqT[DM * DM];
__device__ float g_woT[DM * DM];

// ---------------- helpers ----------------
__device__ __forceinline__ uint32_t rna_u(float x) {
    uint32_t u; asm("cvt.rna.tf32.f32 %0, %1;" : "=r"(u) : "f"(x)); return u;
}
__device__ __forceinline__ float rna_f(float x) { return __uint_as_float(rna_u(x)); }

__device__ __forceinline__ uint32_t smem_addr(const void* p) {
    return (uint32_t)__cvta_generic_to_shared(p);
}
__device__ __forceinline__ void cpasync16(uint32_t s, const void* g) {
    asm volatile("cp.async.cg.shared.global [%0], [%1], 16;" :: "r"(s), "l"(g));
}
#define CP_COMMIT asm volatile("cp.async.commit_group;" ::: "memory")
#define CP_WAIT0  asm volatile("cp.async.wait_group 0;" ::: "memory")
#define CP_WAIT3  asm volatile("cp.async.wait_group 3;" ::: "memory")

// mma.sync m16n8k8 tf32: D += A@B ; A row-major, B col-major
__device__ __forceinline__ void mma8(float* c, const uint32_t* a, const uint32_t* b) {
    asm volatile(
        "mma.sync.aligned.m16n8k8.row.col.f32.tf32.tf32.f32 "
        "{%0,%1,%2,%3}, {%4,%5,%6,%7}, {%8,%9}, {%0,%1,%2,%3};"
        : "+f"(c[0]), "+f"(c[1]), "+f"(c[2]), "+f"(c[3])
        : "r"(a[0]), "r"(a[1]), "r"(a[2]), "r"(a[3]), "r"(b[0]), "r"(b[1]));
}

// ldmatrix: tf32 fragments via b16 matrices.
// A-frag (16x8 tf32): x4. base = &T[tile_row + (lane&15)][kk + ((lane>>4)*4)]
__device__ __forceinline__ void ldsm4(uint32_t* r, uint32_t addr) {
    asm volatile("ldmatrix.sync.aligned.m8n8.x4.shared.b16 {%0,%1,%2,%3}, [%4];"
        : "=r"(r[0]), "=r"(r[1]), "=r"(r[2]), "=r"(r[3]) : "r"(addr));
}
// B-frag (8 rows x 8 k tf32): x2. base = &T[tile_row + (lane&7)][kk + (((lane>>3)&1)*4)]
__device__ __forceinline__ void ldsm2(uint32_t* r, uint32_t addr) {
    asm volatile("ldmatrix.sync.aligned.m8n8.x2.shared.b16 {%0,%1}, [%2];"
        : "=r"(r[0]), "=r"(r[1]) : "r"(addr));
}

// ================= tf32 mma.sync GEMM =================
// C[M,N] = A[M,K] @ Bt[N,K]^T ; CTA tile 128x128, BK=32, 16 warps (warp 32x32).
#define GSTAGES 4
#define GSTR 36                      // padded smem stride (floats): +4 banks/row
#define GSTAGE_F (128*GSTR*2)        // A + B floats per stage
#define GEMM_SMEM (GSTAGES*GSTAGE_F*4)

__global__ __launch_bounds__(512, 1)
void gemm_tf32(const float* __restrict__ A, const float* __restrict__ Bt,
               float* __restrict__ C, int M, int N, int K)
{
    extern __shared__ float sm[];
    const int tid = threadIdx.x, wid = tid >> 5, lane = tid & 31;
    const int g = lane >> 2, tg = lane & 3;
    const int wm = wid >> 2, wn = wid & 3;     // 4 x 4 warp grid
    const int m0 = blockIdx.y * 128, n0 = blockIdx.x * 128;
    const int NC = K >> 5;
    // ldmatrix per-lane offsets (in floats)
    const int lrA = lane & 15, lcA = (lane >> 4) << 2;
    const int lrB = lane & 7,  lcB = ((lane >> 3) & 1) << 2;

    float c[2][4][4];
#pragma unroll
    for (int mt = 0; mt < 2; mt++)
#pragma unroll
        for (int nt = 0; nt < 4; nt++)
#pragma unroll
            for (int j = 0; j < 4; j++) c[mt][nt][j] = 0.f;

    auto load_chunk = [&](int stage, int ch) {
        float* As = sm + stage * GSTAGE_F;
        float* Bs = As + 128 * GSTR;
        const float* Ag = A + (size_t)m0 * K + ch * 32;
        const float* Bg = Bt + (size_t)n0 * K + ch * 32;
#pragma unroll
        for (int i = 0; i < 2; i++) {
            int idx = tid + i * 512;
            int row = idx >> 3, c4 = (idx & 7) << 2;
            cpasync16(smem_addr(As + row * GSTR + c4), Ag + (size_t)row * K + c4);
        }
#pragma unroll
        for (int i = 0; i < 2; i++) {
            int idx = tid + i * 512;
            int row = idx >> 3, c4 = (idx & 7) << 2;
            cpasync16(smem_addr(Bs + row * GSTR + c4), Bg + (size_t)row * K + c4);
        }
    };

    // prologue: 3 chunks in flight
    for (int ch = 0; ch < GSTAGES - 1 && ch < NC; ch++) { load_chunk(ch & 3, ch); CP_COMMIT; }

    for (int ch = 0; ch < NC; ch++) {
        __syncthreads();                   // reads of the stage being overwritten are done
        int pf = ch + GSTAGES - 1;
        if (pf < NC) load_chunk(pf & 3, pf);
        CP_COMMIT;
        CP_WAIT3;                          // chunk ch resident (this thread)
        __syncthreads();                   // visible to all

        const float* As = sm + (ch & 3) * GSTAGE_F;
        const float* Bs = As + 128 * GSTR;
#pragma unroll
        for (int ks = 0; ks < 4; ks++) {
            const int kk = ks * 8;
            uint32_t a[2][4], b[4][2];
#pragma unroll
            for (int mt = 0; mt < 2; mt++)
                ldsm4(a[mt], smem_addr(As + (wm * 32 + mt * 16 + lrA) * GSTR + kk + lcA));
#pragma unroll
            for (int nt = 0; nt < 4; nt++)
                ldsm2(b[nt], smem_addr(Bs + (wn * 32 + nt * 8 + lrB) * GSTR + kk + lcB));
#pragma unroll
            for (int mt = 0; mt < 2; mt++)
#pragma unroll
                for (int nt = 0; nt < 4; nt++)
                    mma8(c[mt][nt], a[mt], b[nt]);
        }
    }

    // epilogue
#pragma unroll
    for (int mt = 0; mt < 2; mt++) {
        int row = m0 + wm * 32 + mt * 16 + g;
#pragma unroll
        for (int nt = 0; nt < 4; nt++) {
            int col = n0 + wn * 32 + nt * 8 + 2 * tg;
            *(float2*)&C[(size_t)row * N + col] = make_float2(c[mt][nt][0], c[mt][nt][1]);
            *(float2*)&C[(size_t)(row + 8) * N + col] = make_float2(c[mt][nt][2], c[mt][nt][3]);
        }
    }
}

// ================= flash attention (causal), tf32 mma.sync =================
// BM=128 q rows, BN=64 kv per tile. 8 warps: 4(m) x 2(n).
#define QSTR 132
#define PSTR 68
#define F_QF (128*QSTR)
#define F_KF (64*QSTR)
#define F_VF (128*PSTR)
#define F_PF (128*PSTR)
#define FLASH_SMEM ((F_QF + F_KF + F_VF + F_PF) * 4)

__global__ __launch_bounds__(256, 1)
void flash_tc(const float* __restrict__ Q, const float* __restrict__ K,
              const float* __restrict__ Vt, float* __restrict__ O)
{
    extern __shared__ float sm[];
    float* Qs = sm;
    float* Ks = Qs + F_QF;
    float* Vs = Ks + F_KF;
    float* Ps = Vs + F_VF;
    __shared__ float ex_m[2][128];
    __shared__ float ex_s[2][128];

    const int tid = threadIdx.x, wid = tid >> 5, lane = tid & 31;
    const int g = lane >> 2, tg = lane & 3;
    const int mw = wid & 3, nw = wid >> 2;
    const int qt = (int)(gridDim.x - 1) - (int)blockIdx.x;   // heavy tiles first
    const int h = blockIdx.y, b = blockIdx.z;
    const int row0 = b * SEQ + qt * 128;
    const int bh = b * NH + h;
    const float scale = 0.08838834764831845f;
    const int lrA = lane & 15, lcA = (lane >> 4) << 2;
    const int lrB = lane & 7,  lcB = ((lane >> 3) & 1) << 2;

    // load Q tile (128 x 128) = 4096 float4
#pragma unroll
    for (int i = 0; i < 16; i++) {
        int idx = tid + i * 256;
        int row = idx >> 5, c4 = (idx & 31) << 2;
        cpasync16(smem_addr(Qs + row * QSTR + c4),
                  Q + (size_t)(row0 + row) * DM + h * HD + c4);
    }
    CP_COMMIT; CP_WAIT0;
    __syncthreads();

    float o[2][8][4];
    float mrun[2][2], lrun[2][2];
#pragma unroll
    for (int mt = 0; mt < 2; mt++) {
        mrun[mt][0] = mrun[mt][1] = -INFINITY;
        lrun[mt][0] = lrun[mt][1] = 0.f;
#pragma unroll
        for (int nt = 0; nt < 8; nt++)
#pragma unroll
            for (int j = 0; j < 4; j++) o[mt][nt][j] = 0.f;
    }

    const int ntiles = 2 * qt + 2;
    for (int jt = 0; jt < ntiles; jt++) {
        const int kv0 = jt * 64;
        __syncthreads();   // prev-iter reads of Ks/Vs/Ps done
        // load K (64 x 128) = 2048 float4
#pragma unroll
        for (int i = 0; i < 8; i++) {
            int idx = tid + i * 256;
            int row = idx >> 5, c4 = (idx & 31) << 2;
            cpasync16(smem_addr(Ks + row * QSTR + c4),
                      K + (size_t)(b * SEQ + kv0 + row) * DM + h * HD + c4);
        }
        // load Vt (128 x 64) = 2048 float4
#pragma unroll
        for (int i = 0; i < 8; i++) {
            int idx = tid + i * 256;
            int row = idx >> 4, c4 = (idx & 15) << 2;
            cpasync16(smem_addr(Vs + row * PSTR + c4),
                      Vt + (size_t)(bh * HD + row) * SEQ + kv0 + c4);
        }
        CP_COMMIT; CP_WAIT0;
        __syncthreads();

        // ---- S = Q @ K^T : warp computes rows mw*32..+31, kv cols nw*32..+31
        float sc[2][4][4];
#pragma unroll
        for (int mt = 0; mt < 2; mt++)
#pragma unroll
            for (int nt = 0; nt < 4; nt++)
#pragma unroll
                for (int j = 0; j < 4; j++) sc[mt][nt][j] = 0.f;

#pragma unroll
        for (int ks = 0; ks < 16; ks++) {
            const int kk = ks * 8;
            uint32_t a[2][4], bfr[4][2];
#pragma unroll
            for (int mt = 0; mt < 2; mt++)
                ldsm4(a[mt], smem_addr(Qs + (mw * 32 + mt * 16 + lrA) * QSTR + kk + lcA));
#pragma unroll
            for (int nt = 0; nt < 4; nt++)
                ldsm2(bfr[nt], smem_addr(Ks + (nw * 32 + nt * 8 + lrB) * QSTR + kk + lcB));
#pragma unroll
            for (int mt = 0; mt < 2; mt++)
#pragma unroll
                for (int nt = 0; nt < 4; nt++)
                    mma8(sc[mt][nt], a[mt], bfr[nt]);
        }

        // ---- scale + causal mask
        const bool need_mask = (jt >= 2 * qt);
#pragma unroll
        for (int mt = 0; mt < 2; mt++)
#pragma unroll
            for (int nt = 0; nt < 4; nt++)
#pragma unroll
                for (int j = 0; j < 4; j++) {
                    float s = sc[mt][nt][j] * scale;
                    if (need_mask) {
                        int qr = qt * 128 + mw * 32 + mt * 16 + g + ((j >= 2) ? 8 : 0);
                        int kc = kv0 + nw * 32 + nt * 8 + 2 * tg + (j & 1);
                        if (kc > qr) s = -1e30f;
                    }
                    sc[mt][nt][j] = s;
                }

        // ---- row max (quad shuffle), cross n-warp via smem
#pragma unroll
        for (int mt = 0; mt < 2; mt++)
#pragma unroll
            for (int hh = 0; hh < 2; hh++) {
                float mx = -INFINITY;
#pragma unroll
                for (int nt = 0; nt < 4; nt++)
                    mx = fmaxf(mx, fmaxf(sc[mt][nt][hh * 2], sc[mt][nt][hh * 2 + 1]));
                mx = fmaxf(mx, __shfl_xor_sync(0xffffffffu, mx, 1));
                mx = fmaxf(mx, __shfl_xor_sync(0xffffffffu, mx, 2));
                ex_m[nw][mw * 32 + mt * 16 + g + hh * 8] = mx;
            }
        __syncthreads();

        // ---- exp, P store, row sums, o rescale
        float fac[2][2];
#pragma unroll
        for (int mt = 0; mt < 2; mt++)
#pragma unroll
            for (int hh = 0; hh < 2; hh++) {
                int rl = mw * 32 + mt * 16 + g + hh * 8;
                float mn = fmaxf(mrun[mt][hh], fmaxf(ex_m[0][rl], ex_m[1][rl]));
                float f = __expf(mrun[mt][hh] - mn);
                mrun[mt][hh] = mn;
                fac[mt][hh] = f;
                float sum = 0.f;
#pragma unroll
                for (int nt = 0; nt < 4; nt++) {
                    float p0 = __expf(sc[mt][nt][hh * 2] - mn);
                    float p1 = __expf(sc[mt][nt][hh * 2 + 1] - mn);
                    sum += p0 + p1;
                    int col = nw * 32 + nt * 8 + 2 * tg;
                    *(float2*)&Ps[rl * PSTR + col] = make_float2(rna_f(p0), rna_f(p1));
                }
                sum += __shfl_xor_sync(0xffffffffu, sum, 1);
                sum += __shfl_xor_sync(0xffffffffu, sum, 2);
                ex_s[nw][rl] = sum;
            }
        // rescale o
#pragma unroll
        for (int mt = 0; mt < 2; mt++)
#pragma unroll
            for (int nt = 0; nt < 8; nt++) {
                o[mt][nt][0] *= fac[mt][0];
                o[mt][nt][1] *= fac[mt][0];
                o[mt][nt][2] *= fac[mt][1];
                o[mt][nt][3] *= fac[mt][1];
            }
        __syncthreads();   // P + ex_s visible
#pragma unroll
        for (int mt = 0; mt < 2; mt++)
#pragma unroll
            for (int hh = 0; hh < 2; hh++) {
                int rl = mw * 32 + mt * 16 + g + hh * 8;
                lrun[mt][hh] = lrun[mt][hh] * fac[mt][hh] + ex_s[0][rl] + ex_s[1][rl];
            }

        // ---- O += P @ V : warp rows mw*32..+31, hd cols nw*64..+63
#pragma unroll
        for (int ks = 0; ks < 8; ks++) {
            const int kk = ks * 8;
            uint32_t a[2][4], bfr[8][2];
#pragma unroll
            for (int mt = 0; mt < 2; mt++)
                ldsm4(a[mt], smem_addr(Ps + (mw * 32 + mt * 16 + lrA) * PSTR + kk + lcA));
#pragma unroll
            for (int nt = 0; nt < 8; nt++)
                ldsm2(bfr[nt], smem_addr(Vs + (nw * 64 + nt * 8 + lrB) * PSTR + kk + lcB));
#pragma unroll
            for (int mt = 0; mt < 2; mt++)
#pragma unroll
                for (int nt = 0; nt < 8; nt++)
                    mma8(o[mt][nt], a[mt], bfr[nt]);
        }
    }

    // ---- epilogue: normalize + rna (feeds tf32 w_out GEMM)
#pragma unroll
    for (int mt = 0; mt < 2; mt++) {
        float inv0 = 1.0f / lrun[mt][0];
        float inv1 = 1.0f / lrun[mt][1];
        int row = row0 + mw * 32 + mt * 16 + g;
#pragma unroll
        for (int nt = 0; nt < 8; nt++) {
            int col = h * HD + nw * 64 + nt * 8 + 2 * tg;
            *(float2*)&O[(size_t)row * DM + col] =
                make_float2(rna_f(o[mt][nt][0] * inv0), rna_f(o[mt][nt][1] * inv0));
            *(float2*)&O[(size_t)(row + 8) * DM + col] =
                make_float2(rna_f(o[mt][nt][2] * inv1), rna_f(o[mt][nt][3] * inv1));
        }
    }
}

// ---------------- small kernels ----------------
__global__ __launch_bounds__(256) void cvtx_kernel(const float* __restrict__ x,
                                                   float* __restrict__ y, int n4)
{
    int i = blockIdx.x * 256 + threadIdx.x;
    if (i >= n4) return;
    float4 v = ((const float4*)x)[i];
    ((float4*)y)[i] = make_float4(rna_f(v.x), rna_f(v.y), rna_f(v.z), rna_f(v.w));
}

__global__ __launch_bounds__(256) void trans_cvt(const float* __restrict__ src,
                                                 float* __restrict__ dst, int R, int C)
{
    __shared__ float t[32][33];
    int c0 = blockIdx.x * 32, r0 = blockIdx.y * 32;
    int tx = threadIdx.x & 31, ty = threadIdx.x >> 5;
#pragma unroll
    for (int i = 0; i < 4; i++)
        t[ty + i * 8][tx] = src[(size_t)(r0 + ty + i * 8) * C + c0 + tx];
    __syncthreads();
#pragma unroll
    for (int i = 0; i < 4; i++)
        dst[(size_t)(c0 + ty + i * 8) * R + r0 + tx] = rna_f(t[tx][ty + i * 8]);
}

__global__ __launch_bounds__(256) void vtrans_kernel(const float* __restrict__ v,
                                                     float* __restrict__ vt)
{
    __shared__ float t[32][33];
    int bh = blockIdx.z;
    int b = bh >> 4, h = bh & 15;
    int s0 = blockIdx.x * 32, d0 = blockIdx.y * 32;
    int tx = threadIdx.x & 31, ty = threadIdx.x >> 5;
#pragma unroll
    for (int i = 0; i < 4; i++)
        t[ty + i * 8][tx] = v[(size_t)(b * SEQ + s0 + ty + i * 8) * DM + h * HD + d0 + tx];
    __syncthreads();
#pragma unroll
    for (int i = 0; i < 4; i++)
        vt[(size_t)(bh * HD + d0 + ty + i * 8) * SEQ + s0 + tx] = rna_f(t[tx][ty + i * 8]);
}

__global__ __launch_bounds__(256) void rmsnorm_kernel(float* __restrict__ x,
                                                      const float* __restrict__ w)
{
    const int row = blockIdx.x;
    float* p = x + (size_t)row * LORA;
    const int t = threadIdx.x;
    float v0 = p[t], v1 = p[t + 256];
    float ss = v0 * v0 + v1 * v1;
#pragma unroll
    for (int o = 16; o; o >>= 1) ss += __shfl_xor_sync(0xffffffffu, ss, o);
    __shared__ float sred[8];
    if ((t & 31) == 0) sred[t >> 5] = ss;
    __syncthreads();
    float tot = 0.f;
#pragma unroll
    for (int i = 0; i < 8; i++) tot += sred[i];
    float inv = rsqrtf(tot * (1.0f / (float)LORA) + 1e-6f);
    p[t]       = rna_f(v0 * inv * w[t]);
    p[t + 256] = rna_f(v1 * inv * w[t + 256]);
}

__global__ __launch_bounds__(256) void rope_kernel(float* __restrict__ t,
                                                   const float* __restrict__ fc,
                                                   const float* __restrict__ fs)
{
    int idx = blockIdx.x * 256 + threadIdx.x;
    if (idx >= ROWS * NH * 64) return;
    int p = idx & 63, h = (idx >> 6) & 15, row = idx >> 10;
    int s = row & (SEQ - 1);
    float c = fc[s * 64 + p], sn = fs[s * 64 + p];
    float* base = t + (size_t)row * DM + h * HD + p * 2;
    float x1 = base[0], x2 = base[1];
    base[0] = rna_f(x1 * c - x2 * sn);
    base[1] = rna_f(x1 * sn + x2 * c);
}

// ---------------- launch ----------------
extern "C" void kernel_launch(void* const* d_in, const int* in_sizes, int n_in,
                              void* d_out, int out_size)
{
    const float* x     = (const float*)d_in[0];
    const float* fcos  = (const float*)d_in[1];
    const float* fsin  = (const float*)d_in[2];
    const float* w_kvc = (const float*)d_in[3];
    const float* kvw   = (const float*)d_in[4];
    const float* w_k   = (const float*)d_in[5];
    const float* w_v   = (const float*)d_in[6];
    const float* w_q   = (const float*)d_in[7];
    const float* w_o   = (const float*)d_in[8];
    float* out = (float*)d_out;

    float *xc, *kvl, *Kb, *Vb, *Qb, *VT, *Ab;
    float *wkvcT, *wkT, *wvT, *wqT, *woT;
    cudaGetSymbolAddress((void**)&xc, g_xc);
    cudaGetSymbolAddress((void**)&kvl, g_kvlat);
    cudaGetSymbolAddress((void**)&Kb, g_k);
    cudaGetSymbolAddress((void**)&Vb, g_v);
    cudaGetSymbolAddress((void**)&Qb, g_q);
    cudaGetSymbolAddress((void**)&VT, g_vT);
    cudaGetSymbolAddress((void**)&Ab, g_attn);
    cudaGetSymbolAddress((void**)&wkvcT, g_wkvcT);
    cudaGetSymbolAddress((void**)&wkT, g_wkT);
    cudaGetSymbolAddress((void**)&wvT, g_wvT);
    cudaGetSymbolAddress((void**)&wqT, g_wqT);
    cudaGetSymbolAddress((void**)&woT, g_woT);

    cudaFuncSetAttribute(gemm_tf32, cudaFuncAttributeMaxDynamicSharedMemorySize, GEMM_SMEM);
    cudaFuncSetAttribute(flash_tc, cudaFuncAttributeMaxDynamicSharedMemorySize, FLASH_SMEM);

    // Launch order arranged so launch #6 (ncu -s 5 -c 1) is the big q-GEMM.
    // 1) tf32-round x
    cvtx_kernel<<<(ROWS * DM / 4 + 255) / 256, 256>>>(x, xc, ROWS * DM / 4);
    // 2-5) transpose + round weights needed early
    trans_cvt<<<dim3(DM / 32, DM / 32), 256>>>(w_q, wqT, DM, DM);
    trans_cvt<<<dim3(LORA / 32, DM / 32), 256>>>(w_kvc, wkvcT, DM, LORA);
    trans_cvt<<<dim3(DM / 32, LORA / 32), 256>>>(w_k, wkT, LORA, DM);
    trans_cvt<<<dim3(DM / 32, LORA / 32), 256>>>(w_v, wvT, LORA, DM);
    // 6) q = x @ w_q [4096, 2048]  <-- profiled launch
    gemm_tf32<<<dim3(DM / 128, ROWS / 128), 512, GEMM_SMEM>>>(xc, wqT, Qb, ROWS, DM, DM);
    // 7) last weight transpose
    trans_cvt<<<dim3(DM / 32, DM / 32), 256>>>(w_o, woT, DM, DM);
    // 8) kv_compressed = x @ w_kvc  [4096, 512]
    gemm_tf32<<<dim3(LORA / 128, ROWS / 128), 512, GEMM_SMEM>>>(xc, wkvcT, kvl, ROWS, LORA, DM);
    rmsnorm_kernel<<<ROWS, 256>>>(kvl, kvw);
    // k, v up-projections [4096, 2048]
    gemm_tf32<<<dim3(DM / 128, ROWS / 128), 512, GEMM_SMEM>>>(kvl, wkT, Kb, ROWS, DM, LORA);
    gemm_tf32<<<dim3(DM / 128, ROWS / 128), 512, GEMM_SMEM>>>(kvl, wvT, Vb, ROWS, DM, LORA);
    // RoPE (+tf32 rounding)
    int rope_n = ROWS * NH * 64;
    rope_kernel<<<(rope_n + 255) / 256, 256>>>(Qb, fcos, fsin);
    rope_kernel<<<(rope_n + 255) / 256, 256>>>(Kb, fcos, fsin);
    // V transpose per (b,h)
    vtrans_kernel<<<dim3(SEQ / 32, HD / 32, BATCH * NH), 256>>>(Vb, VT);
    // flash attention
    flash_tc<<<dim3(SEQ / 128, NH, BATCH), 256, FLASH_SMEM>>>(Qb, Kb, VT, Ab);
    // out = attn @ w_out
    gemm_tf32<<<dim3(DM / 128, ROWS / 128), 512, GEMM_SMEM>>>(Ab, woT, out, ROWS, DM, DM);
}

// round 6
// speedup vs baseline: 2.0547x; 2.0547x over previous
#include <cuda_runtime.h>
#include <cuda_fp16.h>
#include <cstdint>
#include <math.h>

// ---------------- constants ----------------
#define DM 2048
#define NH 16
#define HD 128
#define LORA 512
#define SEQ 2048
#define BATCH 2
#define ROWS (BATCH*SEQ)   // 4096

// ---------------- scratch (fp16 operands, fp32 accum everywhere) ----------------
__device__ __half g_xh[ROWS * DM];
__device__ __half g_kvlat[ROWS * LORA];
__device__ __half g_k[ROWS * DM];
__device__ __half g_v[ROWS * DM];
__device__ __half g_q[ROWS * DM];
__device__ __half g_vT[BATCH * NH * HD * SEQ];
__device__ __half g_attn[ROWS * DM];
__device__ __half g_wkvcT[LORA * DM];
__device__ __half g_wkT[DM * LORA];
__device__ __half g_wvT[DM * LORA];
__device__ __half g_wqT[DM * DM];
__device__ __half g_woT[DM * DM];

// ---------------- helpers ----------------
__device__ __forceinline__ uint32_t smem_addr(const void* p) {
    return (uint32_t)__cvta_generic_to_shared(p);
}
__device__ __forceinline__ void cpasync16(uint32_t s, const void* g) {
    asm volatile("cp.async.cg.shared.global [%0], [%1], 16;" :: "r"(s), "l"(g));
}
#define CP_COMMIT asm volatile("cp.async.commit_group;" ::: "memory")
#define CP_WAIT0  asm volatile("cp.async.wait_group 0;" ::: "memory")
#define CP_WAIT1  asm volatile("cp.async.wait_group 1;" ::: "memory")
#define CP_WAIT3  asm volatile("cp.async.wait_group 3;" ::: "memory")

// mma.sync m16n8k16 fp16 in, fp32 accum: D += A@B ; A row-major, B col-major
__device__ __forceinline__ void mma16(float* c, const uint32_t* a, const uint32_t* b) {
    asm volatile(
        "mma.sync.aligned.m16n8k16.row.col.f32.f16.f16.f32 "
        "{%0,%1,%2,%3}, {%4,%5,%6,%7}, {%8,%9}, {%0,%1,%2,%3};"
        : "+f"(c[0]), "+f"(c[1]), "+f"(c[2]), "+f"(c[3])
        : "r"(a[0]), "r"(a[1]), "r"(a[2]), "r"(a[3]), "r"(b[0]), "r"(b[1]));
}
// A-frag (16 rows x 16 k, fp16): addr = base + (lane&15)*stride + ((lane>>4)*8) halfs
__device__ __forceinline__ void ldsm4(uint32_t* r, uint32_t addr) {
    asm volatile("ldmatrix.sync.aligned.m8n8.x4.shared.b16 {%0,%1,%2,%3}, [%4];"
        : "=r"(r[0]), "=r"(r[1]), "=r"(r[2]), "=r"(r[3]) : "r"(addr));
}
__device__ __forceinline__ uint32_t packh2(float lo, float hi) {
    __half2 h = __floats2half2_rn(lo, hi);
    return *(uint32_t*)&h;
}

// ================= fp16 mma.sync GEMM =================
// C[M,N] = A[M,K] @ Bt[N,K]^T ; CTA 128x128, BK=64, 8 warps (warp 64x32), 4-stage.
#define GSTAGES 4
#define GSTRH 72                       // halfs per row (64 + 8 pad) -> +4 banks/row
#define GSTAGE_H (128*GSTRH*2)         // A + B halfs per stage
#define GEMM_SMEM (GSTAGES*GSTAGE_H*2)

template<typename CT>
__global__ __launch_bounds__(256, 1)
void gemm_f16(const __half* __restrict__ A, const __half* __restrict__ Bt,
              CT* __restrict__ C, int M, int N, int K)
{
    extern __shared__ __half smh[];
    const int tid = threadIdx.x, wid = tid >> 5, lane = tid & 31;
    const int g = lane >> 2, tg = lane & 3;
    const int wm = wid >> 2, wn = wid & 3;     // 2 x 4 warp grid, warp = 64x32
    const int m0 = blockIdx.y * 128, n0 = blockIdx.x * 128;
    const int NC = K >> 6;
    const int lrA = lane & 15, lcA = (lane >> 4) << 3;
    const int lrB4 = (lane & 7) | ((lane >> 4) << 3);
    const int lcB4 = ((lane >> 3) & 1) << 3;

    float c[4][4][4];
#pragma unroll
    for (int mt = 0; mt < 4; mt++)
#pragma unroll
        for (int nt = 0; nt < 4; nt++)
#pragma unroll
            for (int j = 0; j < 4; j++) c[mt][nt][j] = 0.f;

    auto load_chunk = [&](int stage, int ch) {
        __half* As = smh + stage * GSTAGE_H;
        __half* Bs = As + 128 * GSTRH;
        const __half* Ag = A + (size_t)m0 * K + ch * 64;
        const __half* Bg = Bt + (size_t)n0 * K + ch * 64;
#pragma unroll
        for (int i = 0; i < 4; i++) {
            int idx = tid + i * 256;               // 1024 granules of 8 halfs
            int row = idx >> 3, gc = (idx & 7) << 3;
            cpasync16(smem_addr(As + row * GSTRH + gc), Ag + (size_t)row * K + gc);
        }
#pragma unroll
        for (int i = 0; i < 4; i++) {
            int idx = tid + i * 256;
            int row = idx >> 3, gc = (idx & 7) << 3;
            cpasync16(smem_addr(Bs + row * GSTRH + gc), Bg + (size_t)row * K + gc);
        }
    };

    for (int ch = 0; ch < GSTAGES - 1 && ch < NC; ch++) { load_chunk(ch & 3, ch); CP_COMMIT; }

    for (int ch = 0; ch < NC; ch++) {
        __syncthreads();
        int pf = ch + GSTAGES - 1;
        if (pf < NC) load_chunk(pf & 3, pf);
        CP_COMMIT;
        CP_WAIT3;
        __syncthreads();

        const __half* As = smh + (ch & 3) * GSTAGE_H;
        const __half* Bs = As + 128 * GSTRH;
#pragma unroll
        for (int ks = 0; ks < 4; ks++) {
            const int kk = ks * 16;
            uint32_t a[4][4], b[2][4];
#pragma unroll
            for (int mt = 0; mt < 4; mt++)
                ldsm4(a[mt], smem_addr(As + (wm * 64 + mt * 16 + lrA) * GSTRH + kk + lcA));
#pragma unroll
            for (int nt2 = 0; nt2 < 2; nt2++)
                ldsm4(b[nt2], smem_addr(Bs + (wn * 32 + nt2 * 16 + lrB4) * GSTRH + kk + lcB4));
#pragma unroll
            for (int mt = 0; mt < 4; mt++)
#pragma unroll
                for (int nt2 = 0; nt2 < 2; nt2++) {
                    mma16(c[mt][nt2 * 2 + 0], a[mt], b[nt2] + 0);
                    mma16(c[mt][nt2 * 2 + 1], a[mt], b[nt2] + 2);
                }
        }
    }

    // epilogue
#pragma unroll
    for (int mt = 0; mt < 4; mt++) {
        int row = m0 + wm * 64 + mt * 16 + g;
#pragma unroll
        for (int nt = 0; nt < 4; nt++) {
            int col = n0 + wn * 32 + nt * 8 + 2 * tg;
            if constexpr (sizeof(CT) == 2) {
                *(__half2*)&C[(size_t)row * N + col] =
                    __floats2half2_rn(c[mt][nt][0], c[mt][nt][1]);
                *(__half2*)&C[(size_t)(row + 8) * N + col] =
                    __floats2half2_rn(c[mt][nt][2], c[mt][nt][3]);
            } else {
                *(float2*)&C[(size_t)row * N + col] = make_float2(c[mt][nt][0], c[mt][nt][1]);
                *(float2*)&C[(size_t)(row + 8) * N + col] = make_float2(c[mt][nt][2], c[mt][nt][3]);
            }
        }
    }
}

// ================= flash attention (causal), fp16 mma.sync =================
// BM=128 q, BN=64 kv. 8 warps, each owns 16 q rows x full 64 kv. P stays in regs.
// K/V tiles double-buffered; Q loaded once.
#define QSTRH 136                       // 128 + 8 pad
#define VSTRH 72                        // 64 + 8 pad
#define FQ_H (128*QSTRH)
#define FK_H (64*QSTRH)
#define FV_H (128*VSTRH)
#define FLASH_SMEM ((FQ_H + 2*FK_H + 2*FV_H) * 2)

__global__ __launch_bounds__(256, 1)
void flash_f16(const __half* __restrict__ Q, const __half* __restrict__ K,
               const __half* __restrict__ Vt, __half* __restrict__ O)
{
    extern __shared__ __half smh[];
    __half* Qs = smh;
    __half* Ks = Qs + FQ_H;              // 2 buffers
    __half* Vs = Ks + 2 * FK_H;          // 2 buffers

    const int tid = threadIdx.x, wid = tid >> 5, lane = tid & 31;
    const int g = lane >> 2, tg = lane & 3;
    const int qt = (int)(gridDim.x - 1) - (int)blockIdx.x;   // heavy tiles first
    const int h = blockIdx.y, b = blockIdx.z;
    const int row0 = b * SEQ + qt * 128;
    const int bh = b * NH + h;
    const float scale = 0.08838834764831845f;
    const int lrA = lane & 15, lcA = (lane >> 4) << 3;
    const int lrB4 = (lane & 7) | ((lane >> 4) << 3);
    const int lcB4 = ((lane >> 3) & 1) << 3;

    auto issue_tile = [&](int jt) {
        const int kv0 = jt << 6;
        __half* Kb = Ks + (jt & 1) * FK_H;
        __half* Vb = Vs + (jt & 1) * FV_H;
#pragma unroll
        for (int i = 0; i < 4; i++) {           // K: 64 rows x 16 granules
            int idx = tid + i * 256;
            int row = idx >> 4, gc = (idx & 15) << 3;
            cpasync16(smem_addr(Kb + row * QSTRH + gc),
                      K + (size_t)(b * SEQ + kv0 + row) * DM + h * HD + gc);
        }
#pragma unroll
        for (int i = 0; i < 4; i++) {           // Vt: 128 rows x 8 granules
            int idx = tid + i * 256;
            int row = idx >> 3, gc = (idx & 7) << 3;
            cpasync16(smem_addr(Vb + row * VSTRH + gc),
                      Vt + (size_t)(bh * HD + row) * SEQ + kv0 + gc);
        }
    };

    // Q tile: 128 rows x 16 granules = 2048
#pragma unroll
    for (int i = 0; i < 8; i++) {
        int idx = tid + i * 256;
        int row = idx >> 4, gc = (idx & 15) << 3;
        cpasync16(smem_addr(Qs + row * QSTRH + gc),
                  Q + (size_t)(row0 + row) * DM + h * HD + gc);
    }
    CP_COMMIT;
    issue_tile(0);
    CP_COMMIT;

    float o[16][4];
#pragma unroll
    for (int nt = 0; nt < 16; nt++)
#pragma unroll
        for (int j = 0; j < 4; j++) o[nt][j] = 0.f;
    float mrun0 = -INFINITY, mrun1 = -INFINITY, l0 = 0.f, l1 = 0.f;

    const int ntiles = 2 * qt + 2;
    const int qr0 = qt * 128 + wid * 16 + g;
    const int qr1 = qr0 + 8;

    for (int jt = 0; jt < ntiles; jt++) {
        const int kv0 = jt << 6;
        __syncthreads();                       // all warps done with buffer being refilled
        bool pf = (jt + 1 < ntiles);
        if (pf) issue_tile(jt + 1);
        CP_COMMIT;
        if (pf) { CP_WAIT1; } else { CP_WAIT0; }
        __syncthreads();

        const __half* Kb = Ks + (jt & 1) * FK_H;
        const __half* Vb = Vs + (jt & 1) * FV_H;

        // ---- S = Q @ K^T : this warp's 16 q rows x 64 kv
        float sc[8][4];
#pragma unroll
        for (int nt = 0; nt < 8; nt++)
#pragma unroll
            for (int j = 0; j < 4; j++) sc[nt][j] = 0.f;

#pragma unroll
        for (int ks = 0; ks < 8; ks++) {
            const int kk = ks * 16;
            uint32_t a[4], bf[4][4];
            ldsm4(a, smem_addr(Qs + (wid * 16 + lrA) * QSTRH + kk + lcA));
#pragma unroll
            for (int nt2 = 0; nt2 < 4; nt2++)
                ldsm4(bf[nt2], smem_addr(Kb + (nt2 * 16 + lrB4) * QSTRH + kk + lcB4));
#pragma unroll
            for (int nt2 = 0; nt2 < 4; nt2++) {
                mma16(sc[nt2 * 2 + 0], a, bf[nt2] + 0);
                mma16(sc[nt2 * 2 + 1], a, bf[nt2] + 2);
            }
        }

        // ---- scale + causal mask
        const bool need_mask = (jt >= 2 * qt);
#pragma unroll
        for (int nt = 0; nt < 8; nt++) {
            int kc = kv0 + nt * 8 + 2 * tg;
#pragma unroll
            for (int j = 0; j < 4; j++) {
                float s = sc[nt][j] * scale;
                if (need_mask) {
                    int qr = (j >= 2) ? qr1 : qr0;
                    if (kc + (j & 1) > qr) s = -1e30f;
                }
                sc[nt][j] = s;
            }
        }

        // ---- in-warp online softmax (rows g and g+8 of this warp's block)
        float mx0 = -INFINITY, mx1 = -INFINITY;
#pragma unroll
        for (int nt = 0; nt < 8; nt++) {
            mx0 = fmaxf(mx0, fmaxf(sc[nt][0], sc[nt][1]));
            mx1 = fmaxf(mx1, fmaxf(sc[nt][2], sc[nt][3]));
        }
        mx0 = fmaxf(mx0, __shfl_xor_sync(0xffffffffu, mx0, 1));
        mx0 = fmaxf(mx0, __shfl_xor_sync(0xffffffffu, mx0, 2));
        mx1 = fmaxf(mx1, __shfl_xor_sync(0xffffffffu, mx1, 1));
        mx1 = fmaxf(mx1, __shfl_xor_sync(0xffffffffu, mx1, 2));
        float mn0 = fmaxf(mrun0, mx0), mn1 = fmaxf(mrun1, mx1);
        float fac0 = __expf(mrun0 - mn0), fac1 = __expf(mrun1 - mn1);
        mrun0 = mn0; mrun1 = mn1;

        float s0 = 0.f, s1 = 0.f;
#pragma unroll
        for (int nt = 0; nt < 8; nt++) {
            sc[nt][0] = __expf(sc[nt][0] - mn0);
            sc[nt][1] = __expf(sc[nt][1] - mn0);
            sc[nt][2] = __expf(sc[nt][2] - mn1);
            sc[nt][3] = __expf(sc[nt][3] - mn1);
            s0 += sc[nt][0] + sc[nt][1];
            s1 += sc[nt][2] + sc[nt][3];
        }
        s0 += __shfl_xor_sync(0xffffffffu, s0, 1);
        s0 += __shfl_xor_sync(0xffffffffu, s0, 2);
        s1 += __shfl_xor_sync(0xffffffffu, s1, 1);
        s1 += __shfl_xor_sync(0xffffffffu, s1, 2);
        l0 = l0 * fac0 + s0;
        l1 = l1 * fac1 + s1;

#pragma unroll
        for (int nt = 0; nt < 16; nt++) {
            o[nt][0] *= fac0; o[nt][1] *= fac0;
            o[nt][2] *= fac1; o[nt][3] *= fac1;
        }

        // ---- O += P @ V ; P packed straight from sc registers (A-frag layout)
#pragma unroll
        for (int kb = 0; kb < 4; kb++) {
            uint32_t a[4];
            a[0] = packh2(sc[2 * kb][0],     sc[2 * kb][1]);
            a[1] = packh2(sc[2 * kb][2],     sc[2 * kb][3]);
            a[2] = packh2(sc[2 * kb + 1][0], sc[2 * kb + 1][1]);
            a[3] = packh2(sc[2 * kb + 1][2], sc[2 * kb + 1][3]);
            const int kk = kb * 16;
#pragma unroll
            for (int nt2 = 0; nt2 < 8; nt2++) {
                uint32_t bf[4];
                ldsm4(bf, smem_addr(Vb + (nt2 * 16 + lrB4) * VSTRH + kk + lcB4));
                mma16(o[nt2 * 2 + 0], a, bf + 0);
                mma16(o[nt2 * 2 + 1], a, bf + 2);
            }
        }
    }

    // ---- epilogue
    float inv0 = 1.0f / l0, inv1 = 1.0f / l1;
    int row = row0 + wid * 16 + g;
#pragma unroll
    for (int nt = 0; nt < 16; nt++) {
        int col = h * HD + nt * 8 + 2 * tg;
        *(__half2*)&O[(size_t)row * DM + col] =
            __floats2half2_rn(o[nt][0] * inv0, o[nt][1] * inv0);
        *(__half2*)&O[(size_t)(row + 8) * DM + col] =
            __floats2half2_rn(o[nt][2] * inv1, o[nt][3] * inv1);
    }
}

// ---------------- small kernels ----------------
__global__ __launch_bounds__(256) void cvtx_kernel(const float* __restrict__ x,
                                                   __half* __restrict__ y, int n4)
{
    int i = blockIdx.x * 256 + threadIdx.x;
    if (i >= n4) return;
    float4 v = ((const float4*)x)[i];
    ((__half2*)y)[2 * i]     = __floats2half2_rn(v.x, v.y);
    ((__half2*)y)[2 * i + 1] = __floats2half2_rn(v.z, v.w);
}

// src float [R?]: transpose [r,c] -> dst half [c,r]
__global__ __launch_bounds__(256) void trans_cvt(const float* __restrict__ src,
                                                 __half* __restrict__ dst, int R, int C)
{
    __shared__ float t[32][33];
    int c0 = blockIdx.x * 32, r0 = blockIdx.y * 32;
    int tx = threadIdx.x & 31, ty = threadIdx.x >> 5;
#pragma unroll
    for (int i = 0; i < 4; i++)
        t[ty + i * 8][tx] = src[(size_t)(r0 + ty + i * 8) * C + c0 + tx];
    __syncthreads();
#pragma unroll
    for (int i = 0; i < 4; i++)
        dst[(size_t)(c0 + ty + i * 8) * R + r0 + tx] = __float2half_rn(t[tx][ty + i * 8]);
}

__global__ __launch_bounds__(256) void vtrans_kernel(const __half* __restrict__ v,
                                                     __half* __restrict__ vt)
{
    __shared__ float t[32][33];
    int bh = blockIdx.z;
    int b = bh >> 4, h = bh & 15;
    int s0 = blockIdx.x * 32, d0 = blockIdx.y * 32;
    int tx = threadIdx.x & 31, ty = threadIdx.x >> 5;
#pragma unroll
    for (int i = 0; i < 4; i++)
        t[ty + i * 8][tx] = __half2float(v[(size_t)(b * SEQ + s0 + ty + i * 8) * DM + h * HD + d0 + tx]);
    __syncthreads();
#pragma unroll
    for (int i = 0; i < 4; i++)
        vt[(size_t)(bh * HD + d0 + ty + i * 8) * SEQ + s0 + tx] = __float2half_rn(t[tx][ty + i * 8]);
}

__global__ __launch_bounds__(256) void rmsnorm_kernel(__half* __restrict__ x,
                                                      const float* __restrict__ w)
{
    const int row = blockIdx.x;
    __half* p = x + (size_t)row * LORA;
    const int t = threadIdx.x;
    float v0 = __half2float(p[t]), v1 = __half2float(p[t + 256]);
    float ss = v0 * v0 + v1 * v1;
#pragma unroll
    for (int o = 16; o; o >>= 1) ss += __shfl_xor_sync(0xffffffffu, ss, o);
    __shared__ float sred[8];
    if ((t & 31) == 0) sred[t >> 5] = ss;
    __syncthreads();
    float tot = 0.f;
#pragma unroll
    for (int i = 0; i < 8; i++) tot += sred[i];
    float inv = rsqrtf(tot * (1.0f / (float)LORA) + 1e-6f);
    p[t]       = __float2half_rn(v0 * inv * w[t]);
    p[t + 256] = __float2half_rn(v1 * inv * w[t + 256]);
}

__global__ __launch_bounds__(256) void rope_kernel(__half* __restrict__ t,
                                                   const float* __restrict__ fc,
                                                   const float* __restrict__ fs)
{
    int idx = blockIdx.x * 256 + threadIdx.x;
    if (idx >= ROWS * NH * 64) return;
    int p = idx & 63, h = (idx >> 6) & 15, row = idx >> 10;
    int s = row & (SEQ - 1);
    float c = fc[s * 64 + p], sn = fs[s * 64 + p];
    __half2* base = (__half2*)(t + (size_t)row * DM + h * HD + p * 2);
    float2 v = __half22float2(*base);
    *base = __floats2half2_rn(v.x * c - v.y * sn, v.x * sn + v.y * c);
}

// ---------------- launch ----------------
extern "C" void kernel_launch(void* const* d_in, const int* in_sizes, int n_in,
                              void* d_out, int out_size)
{
    const float* x     = (const float*)d_in[0];
    const float* fcos  = (const float*)d_in[1];
    const float* fsin  = (const float*)d_in[2];
    const float* w_kvc = (const float*)d_in[3];
    const float* kvw   = (const float*)d_in[4];
    const float* w_k   = (const float*)d_in[5];
    const float* w_v   = (const float*)d_in[6];
    const float* w_q   = (const float*)d_in[7];
    const float* w_o   = (const float*)d_in[8];
    float* out = (float*)d_out;

    __half *xh, *kvl, *Kb, *Vb, *Qb, *VT, *Ab;
    __half *wkvcT, *wkT, *wvT, *wqT, *woT;
    cudaGetSymbolAddress((void**)&xh, g_xh);
    cudaGetSymbolAddress((void**)&kvl, g_kvlat);
    cudaGetSymbolAddress((void**)&Kb, g_k);
    cudaGetSymbolAddress((void**)&Vb, g_v);
    cudaGetSymbolAddress((void**)&Qb, g_q);
    cudaGetSymbolAddress((void**)&VT, g_vT);
    cudaGetSymbolAddress((void**)&Ab, g_attn);
    cudaGetSymbolAddress((void**)&wkvcT, g_wkvcT);
    cudaGetSymbolAddress((void**)&wkT, g_wkT);
    cudaGetSymbolAddress((void**)&wvT, g_wvT);
    cudaGetSymbolAddress((void**)&wqT, g_wqT);
    cudaGetSymbolAddress((void**)&woT, g_woT);

    cudaFuncSetAttribute(gemm_f16<__half>, cudaFuncAttributeMaxDynamicSharedMemorySize, GEMM_SMEM);
    cudaFuncSetAttribute(gemm_f16<float>, cudaFuncAttributeMaxDynamicSharedMemorySize, GEMM_SMEM);
    cudaFuncSetAttribute(flash_f16, cudaFuncAttributeMaxDynamicSharedMemorySize, FLASH_SMEM);

    // 1) x -> fp16
    cvtx_kernel<<<(ROWS * DM / 4 + 255) / 256, 256>>>(x, xh, ROWS * DM / 4);
    // 2-3) weights needed for q-GEMM
    trans_cvt<<<dim3(DM / 32, DM / 32), 256>>>(w_q, wqT, DM, DM);
    trans_cvt<<<dim3(LORA / 32, DM / 32), 256>>>(w_kvc, wkvcT, DM, LORA);
    // 4) q = x @ w_q  <-- ncu-profiled slot
    gemm_f16<__half><<<dim3(DM / 128, ROWS / 128), 256, GEMM_SMEM>>>(xh, wqT, Qb, ROWS, DM, DM);
    // 5-7) remaining weight transposes
    trans_cvt<<<dim3(DM / 32, LORA / 32), 256>>>(w_k, wkT, LORA, DM);
    trans_cvt<<<dim3(DM / 32, LORA / 32), 256>>>(w_v, wvT, LORA, DM);
    trans_cvt<<<dim3(DM / 32, DM / 32), 256>>>(w_o, woT, DM, DM);
    // 8) kv_compressed = x @ w_kvc  [4096, 512]
    gemm_f16<__half><<<dim3(LORA / 128, ROWS / 128), 256, GEMM_SMEM>>>(xh, wkvcT, kvl, ROWS, LORA, DM);
    // 9) rmsnorm in place (fp32 stats)
    rmsnorm_kernel<<<ROWS, 256>>>(kvl, kvw);
    // 10-11) k, v up-projections [4096, 2048]
    gemm_f16<__half><<<dim3(DM / 128, ROWS / 128), 256, GEMM_SMEM>>>(kvl, wkT, Kb, ROWS, DM, LORA);
    gemm_f16<__half><<<dim3(DM / 128, ROWS / 128), 256, GEMM_SMEM>>>(kvl, wvT, Vb, ROWS, DM, LORA);
    // 12-13) RoPE
    int rope_n = ROWS * NH * 64;
    rope_kernel<<<(rope_n + 255) / 256, 256>>>(Qb, fcos, fsin);
    rope_kernel<<<(rope_n + 255) / 256, 256>>>(Kb, fcos, fsin);
    // 14) V transpose per (b,h)
    vtrans_kernel<<<dim3(SEQ / 32, HD / 32, BATCH * NH), 256>>>(Vb, VT);
    // 15) flash attention
    flash_f16<<<dim3(SEQ / 128, NH, BATCH), 256, FLASH_SMEM>>>(Qb, Kb, VT, Ab);
    // 16) out = attn @ w_out (fp32 output)
    gemm_f16<float><<<dim3(DM / 128, ROWS / 128), 256, GEMM_SMEM>>>(Ab, woT, out, ROWS, DM, DM);
}

// round 7
// speedup vs baseline: 2.3060x; 1.1223x over previous
#include <cuda_runtime.h>
#include <cuda_fp16.h>
#include <cstdint>
#include <math.h>

// ---------------- constants ----------------
#define DM 2048
#define NH 16
#define HD 128
#define LORA 512
#define SEQ 2048
#define BATCH 2
#define ROWS (BATCH*SEQ)   // 4096

// ---------------- scratch (fp16 operands, fp32 accum everywhere) ----------------
__device__ __half g_xh[ROWS * DM];
__device__ __half g_kvlat[ROWS * LORA];
__device__ __half g_k[ROWS * DM];
__device__ __half g_v[ROWS * DM];
__device__ __half g_q[ROWS * DM];
__device__ __half g_vT[BATCH * NH * HD * SEQ];
__device__ __half g_attn[ROWS * DM];
__device__ __half g_wkvcT[LORA * DM];
__device__ __half g_wkT[DM * LORA];
__device__ __half g_wvT[DM * LORA];
__device__ __half g_wqT[DM * DM];
__device__ __half g_woT[DM * DM];

// ---------------- helpers ----------------
__device__ __forceinline__ uint32_t smem_addr(const void* p) {
    return (uint32_t)__cvta_generic_to_shared(p);
}
__device__ __forceinline__ void cpasync16(uint32_t s, const void* g) {
    asm volatile("cp.async.cg.shared.global [%0], [%1], 16;" :: "r"(s), "l"(g));
}
#define CP_COMMIT asm volatile("cp.async.commit_group;" ::: "memory")
#define CP_WAIT0  asm volatile("cp.async.wait_group 0;" ::: "memory")
#define CP_WAIT1  asm volatile("cp.async.wait_group 1;" ::: "memory")

// mma.sync m16n8k16 fp16 in, fp32 accum: D += A@B ; A row-major, B col-major
__device__ __forceinline__ void mma16(float* c, const uint32_t* a, const uint32_t* b) {
    asm volatile(
        "mma.sync.aligned.m16n8k16.row.col.f32.f16.f16.f32 "
        "{%0,%1,%2,%3}, {%4,%5,%6,%7}, {%8,%9}, {%0,%1,%2,%3};"
        : "+f"(c[0]), "+f"(c[1]), "+f"(c[2]), "+f"(c[3])
        : "r"(a[0]), "r"(a[1]), "r"(a[2]), "r"(a[3]), "r"(b[0]), "r"(b[1]));
}
__device__ __forceinline__ void ldsm4(uint32_t* r, uint32_t addr) {
    asm volatile("ldmatrix.sync.aligned.m8n8.x4.shared.b16 {%0,%1,%2,%3}, [%4];"
        : "=r"(r[0]), "=r"(r[1]), "=r"(r[2]), "=r"(r[3]) : "r"(addr));
}
__device__ __forceinline__ uint32_t packh2(float lo, float hi) {
    __half2 h = __floats2half2_rn(lo, hi);
    return *(uint32_t*)&h;
}

// ================= fp16 mma.sync GEMM =================
// C[M,N] = A[M,K] @ Bt[N,K]^T ; CTA 128x128, BK=64, 8 warps (warp 64x32).
// 2-stage pipeline, 72KB smem -> 2 CTAs/SM (16 warps/SM).
#define GSTAGES 2
#define GSTRH 72                       // halfs per row (64 + 8 pad)
#define GSTAGE_H (128*GSTRH*2)         // A + B halfs per stage
#define GEMM_SMEM (GSTAGES*GSTAGE_H*2) // 73728 B

template<typename CT>
__global__ __launch_bounds__(256, 2)
void gemm_f16(const __half* __restrict__ A, const __half* __restrict__ Bt,
              CT* __restrict__ C, int M, int N, int K)
{
    extern __shared__ __half smh[];
    const int tid = threadIdx.x, wid = tid >> 5, lane = tid & 31;
    const int g = lane >> 2, tg = lane & 3;
    const int wm = wid >> 2, wn = wid & 3;     // 2 x 4 warp grid, warp = 64x32
    const int m0 = blockIdx.y * 128, n0 = blockIdx.x * 128;
    const int NC = K >> 6;
    const int lrA = lane & 15, lcA = (lane >> 4) << 3;
    const int lrB4 = (lane & 7) | ((lane >> 4) << 3);
    const int lcB4 = ((lane >> 3) & 1) << 3;

    float c[4][4][4];
#pragma unroll
    for (int mt = 0; mt < 4; mt++)
#pragma unroll
        for (int nt = 0; nt < 4; nt++)
#pragma unroll
            for (int j = 0; j < 4; j++) c[mt][nt][j] = 0.f;

    auto load_chunk = [&](int stage, int ch) {
        __half* As = smh + stage * GSTAGE_H;
        __half* Bs = As + 128 * GSTRH;
        const __half* Ag = A + (size_t)m0 * K + ch * 64;
        const __half* Bg = Bt + (size_t)n0 * K + ch * 64;
#pragma unroll
        for (int i = 0; i < 4; i++) {
            int idx = tid + i * 256;               // 1024 granules of 8 halfs
            int row = idx >> 3, gc = (idx & 7) << 3;
            cpasync16(smem_addr(As + row * GSTRH + gc), Ag + (size_t)row * K + gc);
        }
#pragma unroll
        for (int i = 0; i < 4; i++) {
            int idx = tid + i * 256;
            int row = idx >> 3, gc = (idx & 7) << 3;
            cpasync16(smem_addr(Bs + row * GSTRH + gc), Bg + (size_t)row * K + gc);
        }
    };

    load_chunk(0, 0);
    CP_COMMIT;

    for (int ch = 0; ch < NC; ch++) {
        int pf = ch + 1;
        if (pf < NC) { load_chunk(pf & 1, pf); CP_COMMIT; CP_WAIT1; }
        else         { CP_WAIT0; }
        __syncthreads();

        const __half* As = smh + (ch & 1) * GSTAGE_H;
        const __half* Bs = As + 128 * GSTRH;
#pragma unroll
        for (int ks = 0; ks < 4; ks++) {
            const int kk = ks * 16;
            uint32_t a[4][4], b[2][4];
#pragma unroll
            for (int mt = 0; mt < 4; mt++)
                ldsm4(a[mt], smem_addr(As + (wm * 64 + mt * 16 + lrA) * GSTRH + kk + lcA));
#pragma unroll
            for (int nt2 = 0; nt2 < 2; nt2++)
                ldsm4(b[nt2], smem_addr(Bs + (wn * 32 + nt2 * 16 + lrB4) * GSTRH + kk + lcB4));
#pragma unroll
            for (int mt = 0; mt < 4; mt++)
#pragma unroll
                for (int nt2 = 0; nt2 < 2; nt2++) {
                    mma16(c[mt][nt2 * 2 + 0], a[mt], b[nt2] + 0);
                    mma16(c[mt][nt2 * 2 + 1], a[mt], b[nt2] + 2);
                }
        }
        __syncthreads();   // all reads of this stage done before it is refilled
    }

    // epilogue
#pragma unroll
    for (int mt = 0; mt < 4; mt++) {
        int row = m0 + wm * 64 + mt * 16 + g;
#pragma unroll
        for (int nt = 0; nt < 4; nt++) {
            int col = n0 + wn * 32 + nt * 8 + 2 * tg;
            if constexpr (sizeof(CT) == 2) {
                *(__half2*)&C[(size_t)row * N + col] =
                    __floats2half2_rn(c[mt][nt][0], c[mt][nt][1]);
                *(__half2*)&C[(size_t)(row + 8) * N + col] =
                    __floats2half2_rn(c[mt][nt][2], c[mt][nt][3]);
            } else {
                *(float2*)&C[(size_t)row * N + col] = make_float2(c[mt][nt][0], c[mt][nt][1]);
                *(float2*)&C[(size_t)(row + 8) * N + col] = make_float2(c[mt][nt][2], c[mt][nt][3]);
            }
        }
    }
}

// ================= flash attention (causal), fp16 mma.sync =================
// BM=128 q, BN=64 kv. 8 warps, each owns 16 q rows x full 64 kv. P stays in regs.
// K/V tiles double-buffered; Q loaded once.
#define QSTRH 136                       // 128 + 8 pad
#define VSTRH 72                        // 64 + 8 pad
#define FQ_H (128*QSTRH)
#define FK_H (64*QSTRH)
#define FV_H (128*VSTRH)
#define FLASH_SMEM ((FQ_H + 2*FK_H + 2*FV_H) * 2)

__global__ __launch_bounds__(256, 1)
void flash_f16(const __half* __restrict__ Q, const __half* __restrict__ K,
               const __half* __restrict__ Vt, __half* __restrict__ O)
{
    extern __shared__ __half smh[];
    __half* Qs = smh;
    __half* Ks = Qs + FQ_H;              // 2 buffers
    __half* Vs = Ks + 2 * FK_H;          // 2 buffers

    const int tid = threadIdx.x, wid = tid >> 5, lane = tid & 31;
    const int g = lane >> 2, tg = lane & 3;
    const int qt = (int)(gridDim.x - 1) - (int)blockIdx.x;   // heavy tiles first
    const int h = blockIdx.y, b = blockIdx.z;
    const int row0 = b * SEQ + qt * 128;
    const int bh = b * NH + h;
    const float scale = 0.08838834764831845f;
    const int lrA = lane & 15, lcA = (lane >> 4) << 3;
    const int lrB4 = (lane & 7) | ((lane >> 4) << 3);
    const int lcB4 = ((lane >> 3) & 1) << 3;

    auto issue_tile = [&](int jt) {
        const int kv0 = jt << 6;
        __half* Kb = Ks + (jt & 1) * FK_H;
        __half* Vb = Vs + (jt & 1) * FV_H;
#pragma unroll
        for (int i = 0; i < 4; i++) {           // K: 64 rows x 16 granules
            int idx = tid + i * 256;
            int row = idx >> 4, gc = (idx & 15) << 3;
            cpasync16(smem_addr(Kb + row * QSTRH + gc),
                      K + (size_t)(b * SEQ + kv0 + row) * DM + h * HD + gc);
        }
#pragma unroll
        for (int i = 0; i < 4; i++) {           // Vt: 128 rows x 8 granules
            int idx = tid + i * 256;
            int row = idx >> 3, gc = (idx & 7) << 3;
            cpasync16(smem_addr(Vb + row * VSTRH + gc),
                      Vt + (size_t)(bh * HD + row) * SEQ + kv0 + gc);
        }
    };

    // Q tile: 128 rows x 16 granules = 2048
#pragma unroll
    for (int i = 0; i < 8; i++) {
        int idx = tid + i * 256;
        int row = idx >> 4, gc = (idx & 15) << 3;
        cpasync16(smem_addr(Qs + row * QSTRH + gc),
                  Q + (size_t)(row0 + row) * DM + h * HD + gc);
    }
    CP_COMMIT;
    issue_tile(0);
    CP_COMMIT;

    float o[16][4];
#pragma unroll
    for (int nt = 0; nt < 16; nt++)
#pragma unroll
        for (int j = 0; j < 4; j++) o[nt][j] = 0.f;
    float mrun0 = -INFINITY, mrun1 = -INFINITY, l0 = 0.f, l1 = 0.f;

    const int ntiles = 2 * qt + 2;
    const int qr0 = qt * 128 + wid * 16 + g;
    const int qr1 = qr0 + 8;

    for (int jt = 0; jt < ntiles; jt++) {
        const int kv0 = jt << 6;
        __syncthreads();                       // all warps done with buffer being refilled
        bool pf = (jt + 1 < ntiles);
        if (pf) issue_tile(jt + 1);
        CP_COMMIT;
        if (pf) { CP_WAIT1; } else { CP_WAIT0; }
        __syncthreads();

        const __half* Kb = Ks + (jt & 1) * FK_H;
        const __half* Vb = Vs + (jt & 1) * FV_H;

        // ---- S = Q @ K^T : this warp's 16 q rows x 64 kv
        float sc[8][4];
#pragma unroll
        for (int nt = 0; nt < 8; nt++)
#pragma unroll
            for (int j = 0; j < 4; j++) sc[nt][j] = 0.f;

#pragma unroll
        for (int ks = 0; ks < 8; ks++) {
            const int kk = ks * 16;
            uint32_t a[4], bf[4][4];
            ldsm4(a, smem_addr(Qs + (wid * 16 + lrA) * QSTRH + kk + lcA));
#pragma unroll
            for (int nt2 = 0; nt2 < 4; nt2++)
                ldsm4(bf[nt2], smem_addr(Kb + (nt2 * 16 + lrB4) * QSTRH + kk + lcB4));
#pragma unroll
            for (int nt2 = 0; nt2 < 4; nt2++) {
                mma16(sc[nt2 * 2 + 0], a, bf[nt2] + 0);
                mma16(sc[nt2 * 2 + 1], a, bf[nt2] + 2);
            }
        }

        // ---- scale + causal mask
        const bool need_mask = (jt >= 2 * qt);
#pragma unroll
        for (int nt = 0; nt < 8; nt++) {
            int kc = kv0 + nt * 8 + 2 * tg;
#pragma unroll
            for (int j = 0; j < 4; j++) {
                float s = sc[nt][j] * scale;
                if (need_mask) {
                    int qr = (j >= 2) ? qr1 : qr0;
                    if (kc + (j & 1) > qr) s = -1e30f;
                }
                sc[nt][j] = s;
            }
        }

        // ---- in-warp online softmax (rows g and g+8 of this warp's block)
        float mx0 = -INFINITY, mx1 = -INFINITY;
#pragma unroll
        for (int nt = 0; nt < 8; nt++) {
            mx0 = fmaxf(mx0, fmaxf(sc[nt][0], sc[nt][1]));
            mx1 = fmaxf(mx1, fmaxf(sc[nt][2], sc[nt][3]));
        }
        mx0 = fmaxf(mx0, __shfl_xor_sync(0xffffffffu, mx0, 1));
        mx0 = fmaxf(mx0, __shfl_xor_sync(0xffffffffu, mx0, 2));
        mx1 = fmaxf(mx1, __shfl_xor_sync(0xffffffffu, mx1, 1));
        mx1 = fmaxf(mx1, __shfl_xor_sync(0xffffffffu, mx1, 2));
        float mn0 = fmaxf(mrun0, mx0), mn1 = fmaxf(mrun1, mx1);
        float fac0 = __expf(mrun0 - mn0), fac1 = __expf(mrun1 - mn1);
        mrun0 = mn0; mrun1 = mn1;

        float s0 = 0.f, s1 = 0.f;
#pragma unroll
        for (int nt = 0; nt < 8; nt++) {
            sc[nt][0] = __expf(sc[nt][0] - mn0);
            sc[nt][1] = __expf(sc[nt][1] - mn0);
            sc[nt][2] = __expf(sc[nt][2] - mn1);
            sc[nt][3] = __expf(sc[nt][3] - mn1);
            s0 += sc[nt][0] + sc[nt][1];
            s1 += sc[nt][2] + sc[nt][3];
        }
        s0 += __shfl_xor_sync(0xffffffffu, s0, 1);
        s0 += __shfl_xor_sync(0xffffffffu, s0, 2);
        s1 += __shfl_xor_sync(0xffffffffu, s1, 1);
        s1 += __shfl_xor_sync(0xffffffffu, s1, 2);
        l0 = l0 * fac0 + s0;
        l1 = l1 * fac1 + s1;

#pragma unroll
        for (int nt = 0; nt < 16; nt++) {
            o[nt][0] *= fac0; o[nt][1] *= fac0;
            o[nt][2] *= fac1; o[nt][3] *= fac1;
        }

        // ---- O += P @ V ; P packed straight from sc registers (A-frag layout)
#pragma unroll
        for (int kb = 0; kb < 4; kb++) {
            uint32_t a[4];
            a[0] = packh2(sc[2 * kb][0],     sc[2 * kb][1]);
            a[1] = packh2(sc[2 * kb][2],     sc[2 * kb][3]);
            a[2] = packh2(sc[2 * kb + 1][0], sc[2 * kb + 1][1]);
            a[3] = packh2(sc[2 * kb + 1][2], sc[2 * kb + 1][3]);
            const int kk = kb * 16;
#pragma unroll
            for (int nt2 = 0; nt2 < 8; nt2++) {
                uint32_t bf[4];
                ldsm4(bf, smem_addr(Vb + (nt2 * 16 + lrB4) * VSTRH + kk + lcB4));
                mma16(o[nt2 * 2 + 0], a, bf + 0);
                mma16(o[nt2 * 2 + 1], a, bf + 2);
            }
        }
    }

    // ---- epilogue
    float inv0 = 1.0f / l0, inv1 = 1.0f / l1;
    int row = row0 + wid * 16 + g;
#pragma unroll
    for (int nt = 0; nt < 16; nt++) {
        int col = h * HD + nt * 8 + 2 * tg;
        *(__half2*)&O[(size_t)row * DM + col] =
            __floats2half2_rn(o[nt][0] * inv0, o[nt][1] * inv0);
        *(__half2*)&O[(size_t)(row + 8) * DM + col] =
            __floats2half2_rn(o[nt][2] * inv1, o[nt][3] * inv1);
    }
}

// ---------------- small kernels ----------------
__global__ __launch_bounds__(256) void cvtx_kernel(const float* __restrict__ x,
                                                   __half* __restrict__ y, int n4)
{
    int i = blockIdx.x * 256 + threadIdx.x;
    if (i >= n4) return;
    float4 v = ((const float4*)x)[i];
    ((__half2*)y)[2 * i]     = __floats2half2_rn(v.x, v.y);
    ((__half2*)y)[2 * i + 1] = __floats2half2_rn(v.z, v.w);
}

// src float: transpose [r,c] -> dst half [c,r]
__global__ __launch_bounds__(256) void trans_cvt(const float* __restrict__ src,
                                                 __half* __restrict__ dst, int R, int C)
{
    __shared__ float t[32][33];
    int c0 = blockIdx.x * 32, r0 = blockIdx.y * 32;
    int tx = threadIdx.x & 31, ty = threadIdx.x >> 5;
#pragma unroll
    for (int i = 0; i < 4; i++)
        t[ty + i * 8][tx] = src[(size_t)(r0 + ty + i * 8) * C + c0 + tx];
    __syncthreads();
#pragma unroll
    for (int i = 0; i < 4; i++)
        dst[(size_t)(c0 + ty + i * 8) * R + r0 + tx] = __float2half_rn(t[tx][ty + i * 8]);
}

__global__ __launch_bounds__(256) void vtrans_kernel(const __half* __restrict__ v,
                                                     __half* __restrict__ vt)
{
    __shared__ float t[32][33];
    int bh = blockIdx.z;
    int b = bh >> 4, h = bh & 15;
    int s0 = blockIdx.x * 32, d0 = blockIdx.y * 32;
    int tx = threadIdx.x & 31, ty = threadIdx.x >> 5;
#pragma unroll
    for (int i = 0; i < 4; i++)
        t[ty + i * 8][tx] = __half2float(v[(size_t)(b * SEQ + s0 + ty + i * 8) * DM + h * HD + d0 + tx]);
    __syncthreads();
#pragma unroll
    for (int i = 0; i < 4; i++)
        vt[(size_t)(bh * HD + d0 + ty + i * 8) * SEQ + s0 + tx] = __float2half_rn(t[tx][ty + i * 8]);
}

__global__ __launch_bounds__(256) void rmsnorm_kernel(__half* __restrict__ x,
                                                      const float* __restrict__ w)
{
    const int row = blockIdx.x;
    __half* p = x + (size_t)row * LORA;
    const int t = threadIdx.x;
    float v0 = __half2float(p[t]), v1 = __half2float(p[t + 256]);
    float ss = v0 * v0 + v1 * v1;
#pragma unroll
    for (int o = 16; o; o >>= 1) ss += __shfl_xor_sync(0xffffffffu, ss, o);
    __shared__ float sred[8];
    if ((t & 31) == 0) sred[t >> 5] = ss;
    __syncthreads();
    float tot = 0.f;
#pragma unroll
    for (int i = 0; i < 8; i++) tot += sred[i];
    float inv = rsqrtf(tot * (1.0f / (float)LORA) + 1e-6f);
    p[t]       = __float2half_rn(v0 * inv * w[t]);
    p[t + 256] = __float2half_rn(v1 * inv * w[t + 256]);
}

__global__ __launch_bounds__(256) void rope_kernel(__half* __restrict__ t,
                                                   const float* __restrict__ fc,
                                                   const float* __restrict__ fs)
{
    int idx = blockIdx.x * 256 + threadIdx.x;
    if (idx >= ROWS * NH * 64) return;
    int p = idx & 63, h = (idx >> 6) & 15, row = idx >> 10;
    int s = row & (SEQ - 1);
    float c = fc[s * 64 + p], sn = fs[s * 64 + p];
    __half2* base = (__half2*)(t + (size_t)row * DM + h * HD + p * 2);
    float2 v = __half22float2(*base);
    *base = __floats2half2_rn(v.x * c - v.y * sn, v.x * sn + v.y * c);
}

// ---------------- launch ----------------
extern "C" void kernel_launch(void* const* d_in, const int* in_sizes, int n_in,
                              void* d_out, int out_size)
{
    const float* x     = (const float*)d_in[0];
    const float* fcos  = (const float*)d_in[1];
    const float* fsin  = (const float*)d_in[2];
    const float* w_kvc = (const float*)d_in[3];
    const float* kvw   = (const float*)d_in[4];
    const float* w_k   = (const float*)d_in[5];
    const float* w_v   = (const float*)d_in[6];
    const float* w_q   = (const float*)d_in[7];
    const float* w_o   = (const float*)d_in[8];
    float* out = (float*)d_out;

    __half *xh, *kvl, *Kb, *Vb, *Qb, *VT, *Ab;
    __half *wkvcT, *wkT, *wvT, *wqT, *woT;
    cudaGetSymbolAddress((void**)&xh, g_xh);
    cudaGetSymbolAddress((void**)&kvl, g_kvlat);
    cudaGetSymbolAddress((void**)&Kb, g_k);
    cudaGetSymbolAddress((void**)&Vb, g_v);
    cudaGetSymbolAddress((void**)&Qb, g_q);
    cudaGetSymbolAddress((void**)&VT, g_vT);
    cudaGetSymbolAddress((void**)&Ab, g_attn);
    cudaGetSymbolAddress((void**)&wkvcT, g_wkvcT);
    cudaGetSymbolAddress((void**)&wkT, g_wkT);
    cudaGetSymbolAddress((void**)&wvT, g_wvT);
    cudaGetSymbolAddress((void**)&wqT, g_wqT);
    cudaGetSymbolAddress((void**)&woT, g_woT);

    cudaFuncSetAttribute(gemm_f16<__half>, cudaFuncAttributeMaxDynamicSharedMemorySize, GEMM_SMEM);
    cudaFuncSetAttribute(gemm_f16<float>, cudaFuncAttributeMaxDynamicSharedMemorySize, GEMM_SMEM);
    cudaFuncSetAttribute(flash_f16, cudaFuncAttributeMaxDynamicSharedMemorySize, FLASH_SMEM);

    // 1) x -> fp16
    cvtx_kernel<<<(ROWS * DM / 4 + 255) / 256, 256>>>(x, xh, ROWS * DM / 4);
    // 2-3) weights needed for q-GEMM
    trans_cvt<<<dim3(DM / 32, DM / 32), 256>>>(w_q, wqT, DM, DM);
    trans_cvt<<<dim3(LORA / 32, DM / 32), 256>>>(w_kvc, wkvcT, DM, LORA);
    // 4) q = x @ w_q  <-- ncu-profiled slot
    gemm_f16<__half><<<dim3(DM / 128, ROWS / 128), 256, GEMM_SMEM>>>(xh, wqT, Qb, ROWS, DM, DM);
    // 5-7) remaining weight transposes
    trans_cvt<<<dim3(DM / 32, LORA / 32), 256>>>(w_k, wkT, LORA, DM);
    trans_cvt<<<dim3(DM / 32, LORA / 32), 256>>>(w_v, wvT, LORA, DM);
    trans_cvt<<<dim3(DM / 32, DM / 32), 256>>>(w_o, woT, DM, DM);
    // 8) kv_compressed = x @ w_kvc  [4096, 512]
    gemm_f16<__half><<<dim3(LORA / 128, ROWS / 128), 256, GEMM_SMEM>>>(xh, wkvcT, kvl, ROWS, LORA, DM);
    // 9) rmsnorm in place (fp32 stats)
    rmsnorm_kernel<<<ROWS, 256>>>(kvl, kvw);
    // 10-11) k, v up-projections [4096, 2048]
    gemm_f16<__half><<<dim3(DM / 128, ROWS / 128), 256, GEMM_SMEM>>>(kvl, wkT, Kb, ROWS, DM, LORA);
    gemm_f16<__half><<<dim3(DM / 128, ROWS / 128), 256, GEMM_SMEM>>>(kvl, wvT, Vb, ROWS, DM, LORA);
    // 12-13) RoPE
    int rope_n = ROWS * NH * 64;
    rope_kernel<<<(rope_n + 255) / 256, 256>>>(Qb, fcos, fsin);
    rope_kernel<<<(rope_n + 255) / 256, 256>>>(Kb, fcos, fsin);
    // 14) V transpose per (b,h)
    vtrans_kernel<<<dim3(SEQ / 32, HD / 32, BATCH * NH), 256>>>(Vb, VT);
    // 15) flash attention
    flash_f16<<<dim3(SEQ / 128, NH, BATCH), 256, FLASH_SMEM>>>(Qb, Kb, VT, Ab);
    // 16) out = attn @ w_out (fp32 output)
    gemm_f16<float><<<dim3(DM / 128, ROWS / 128), 256, GEMM_SMEM>>>(Ab, woT, out, ROWS, DM, DM);
}

// round 8
// speedup vs baseline: 2.3646x; 1.0254x over previous
#include <cuda_runtime.h>
#include <cuda_fp16.h>
#include <cstdint>
#include <math.h>

// ---------------- constants ----------------
#define DM 2048
#define NH 16
#define HD 128
#define LORA 512
#define SEQ 2048
#define BATCH 2
#define ROWS (BATCH*SEQ)   // 4096

// ---------------- scratch (fp16 operands, fp32 accum everywhere) ----------------
__device__ __half g_xh[ROWS * DM];
__device__ __half g_kvlat[ROWS * LORA];
__device__ __half g_k[ROWS * DM];
__device__ __half g_v[ROWS * DM];
__device__ __half g_q[ROWS * DM];
__device__ __half g_attn[ROWS * DM];
__device__ __half g_wkvcT[LORA * DM];
__device__ __half g_wkT[DM * LORA];
__device__ __half g_wvT[DM * LORA];
__device__ __half g_wqT[DM * DM];
__device__ __half g_woT[DM * DM];

// ---------------- helpers ----------------
__device__ __forceinline__ uint32_t smem_addr(const void* p) {
    return (uint32_t)__cvta_generic_to_shared(p);
}
__device__ __forceinline__ void cpasync16(uint32_t s, const void* g) {
    asm volatile("cp.async.cg.shared.global [%0], [%1], 16;" :: "r"(s), "l"(g));
}
#define CP_COMMIT asm volatile("cp.async.commit_group;" ::: "memory")
#define CP_WAIT0  asm volatile("cp.async.wait_group 0;" ::: "memory")
#define CP_WAIT1  asm volatile("cp.async.wait_group 1;" ::: "memory")

// mma.sync m16n8k16 fp16 in, fp32 accum: D += A@B ; A row-major, B col-major
__device__ __forceinline__ void mma16(float* c, const uint32_t* a, const uint32_t* b) {
    asm volatile(
        "mma.sync.aligned.m16n8k16.row.col.f32.f16.f16.f32 "
        "{%0,%1,%2,%3}, {%4,%5,%6,%7}, {%8,%9}, {%0,%1,%2,%3};"
        : "+f"(c[0]), "+f"(c[1]), "+f"(c[2]), "+f"(c[3])
        : "r"(a[0]), "r"(a[1]), "r"(a[2]), "r"(a[3]), "r"(b[0]), "r"(b[1]));
}
__device__ __forceinline__ void ldsm4(uint32_t* r, uint32_t addr) {
    asm volatile("ldmatrix.sync.aligned.m8n8.x4.shared.b16 {%0,%1,%2,%3}, [%4];"
        : "=r"(r[0]), "=r"(r[1]), "=r"(r[2]), "=r"(r[3]) : "r"(addr));
}
__device__ __forceinline__ void ldsm4t(uint32_t* r, uint32_t addr) {
    asm volatile("ldmatrix.sync.aligned.m8n8.x4.trans.shared.b16 {%0,%1,%2,%3}, [%4];"
        : "=r"(r[0]), "=r"(r[1]), "=r"(r[2]), "=r"(r[3]) : "r"(addr));
}
__device__ __forceinline__ uint32_t packh2(float lo, float hi) {
    __half2 h = __floats2half2_rn(lo, hi);
    return *(uint32_t*)&h;
}

// ================= fp16 mma.sync GEMM =================
// C[M,N] = A[M,K] @ Bt[N,K]^T ; CTA 128x128, BK=64, 8 warps (warp 64x32).
// 2-stage pipeline, 72KB smem -> 2 CTAs/SM. Optional fused RoPE epilogue
// (valid when N == DM and columns are [head][hd] blocks of 128).
#define GSTAGES 2
#define GSTRH 72                       // halfs per row (64 + 8 pad)
#define GSTAGE_H (128*GSTRH*2)         // A + B halfs per stage
#define GEMM_SMEM (GSTAGES*GSTAGE_H*2) // 73728 B

template<typename CT, bool ROPE>
__global__ __launch_bounds__(256, 2)
void gemm_f16(const __half* __restrict__ A, const __half* __restrict__ Bt,
              CT* __restrict__ C, int M, int N, int K,
              const float* __restrict__ fc, const float* __restrict__ fs)
{
    extern __shared__ __half smh[];
    const int tid = threadIdx.x, wid = tid >> 5, lane = tid & 31;
    const int g = lane >> 2, tg = lane & 3;
    const int wm = wid >> 2, wn = wid & 3;     // 2 x 4 warp grid, warp = 64x32
    const int m0 = blockIdx.y * 128, n0 = blockIdx.x * 128;
    const int NC = K >> 6;
    const int lrA = lane & 15, lcA = (lane >> 4) << 3;
    const int lrB4 = (lane & 7) | ((lane >> 4) << 3);
    const int lcB4 = ((lane >> 3) & 1) << 3;

    float c[4][4][4];
#pragma unroll
    for (int mt = 0; mt < 4; mt++)
#pragma unroll
        for (int nt = 0; nt < 4; nt++)
#pragma unroll
            for (int j = 0; j < 4; j++) c[mt][nt][j] = 0.f;

    auto load_chunk = [&](int stage, int ch) {
        __half* As = smh + stage * GSTAGE_H;
        __half* Bs = As + 128 * GSTRH;
        const __half* Ag = A + (size_t)m0 * K + ch * 64;
        const __half* Bg = Bt + (size_t)n0 * K + ch * 64;
#pragma unroll
        for (int i = 0; i < 4; i++) {
            int idx = tid + i * 256;               // 1024 granules of 8 halfs
            int row = idx >> 3, gc = (idx & 7) << 3;
            cpasync16(smem_addr(As + row * GSTRH + gc), Ag + (size_t)row * K + gc);
        }
#pragma unroll
        for (int i = 0; i < 4; i++) {
            int idx = tid + i * 256;
            int row = idx >> 3, gc = (idx & 7) << 3;
            cpasync16(smem_addr(Bs + row * GSTRH + gc), Bg + (size_t)row * K + gc);
        }
    };

    load_chunk(0, 0);
    CP_COMMIT;

    for (int ch = 0; ch < NC; ch++) {
        int pf = ch + 1;
        if (pf < NC) { load_chunk(pf & 1, pf); CP_COMMIT; CP_WAIT1; }
        else         { CP_WAIT0; }
        __syncthreads();

        const __half* As = smh + (ch & 1) * GSTAGE_H;
        const __half* Bs = As + 128 * GSTRH;
#pragma unroll
        for (int ks = 0; ks < 4; ks++) {
            const int kk = ks * 16;
            uint32_t a[4][4], b[2][4];
#pragma unroll
            for (int mt = 0; mt < 4; mt++)
                ldsm4(a[mt], smem_addr(As + (wm * 64 + mt * 16 + lrA) * GSTRH + kk + lcA));
#pragma unroll
            for (int nt2 = 0; nt2 < 2; nt2++)
                ldsm4(b[nt2], smem_addr(Bs + (wn * 32 + nt2 * 16 + lrB4) * GSTRH + kk + lcB4));
#pragma unroll
            for (int mt = 0; mt < 4; mt++)
#pragma unroll
                for (int nt2 = 0; nt2 < 2; nt2++) {
                    mma16(c[mt][nt2 * 2 + 0], a[mt], b[nt2] + 0);
                    mma16(c[mt][nt2 * 2 + 1], a[mt], b[nt2] + 2);
                }
        }
        __syncthreads();   // all reads of this stage done before it is refilled
    }

    // epilogue (+ optional fused RoPE on fp32 accumulators)
#pragma unroll
    for (int mt = 0; mt < 4; mt++) {
        int row = m0 + wm * 64 + mt * 16 + g;
#pragma unroll
        for (int nt = 0; nt < 4; nt++) {
            int col = n0 + wn * 32 + nt * 8 + 2 * tg;
            float v0 = c[mt][nt][0], v1 = c[mt][nt][1];
            float v2 = c[mt][nt][2], v3 = c[mt][nt][3];
            if (ROPE) {
                int p = (col & 127) >> 1;
                int s0 = row & (SEQ - 1);
                int s1 = (row + 8) & (SEQ - 1);
                float c0 = fc[s0 * 64 + p], n0v = fs[s0 * 64 + p];
                float c1 = fc[s1 * 64 + p], n1v = fs[s1 * 64 + p];
                float t0 = v0 * c0 - v1 * n0v, t1 = v0 * n0v + v1 * c0;
                float t2 = v2 * c1 - v3 * n1v, t3 = v2 * n1v + v3 * c1;
                v0 = t0; v1 = t1; v2 = t2; v3 = t3;
            }
            if constexpr (sizeof(CT) == 2) {
                *(__half2*)&C[(size_t)row * N + col] = __floats2half2_rn(v0, v1);
                *(__half2*)&C[(size_t)(row + 8) * N + col] = __floats2half2_rn(v2, v3);
            } else {
                *(float2*)&C[(size_t)row * N + col] = make_float2(v0, v1);
                *(float2*)&C[(size_t)(row + 8) * N + col] = make_float2(v2, v3);
            }
        }
    }
}

// ================= flash attention (causal), fp16 mma.sync =================
// BM=128 q, BN=64 kv. 8 warps, each owns 16 q rows x full 64 kv. P stays in regs.
// K and V both loaded in natural [seq][hd] layout (V B-frags via ldmatrix.trans).
// K/V tiles double-buffered; Q loaded once.
#define QSTRH 136                       // 128 + 8 pad
#define FQ_H (128*QSTRH)
#define FK_H (64*QSTRH)
#define FLASH_SMEM ((FQ_H + 4*FK_H) * 2)

__global__ __launch_bounds__(256, 1)
void flash_f16(const __half* __restrict__ Q, const __half* __restrict__ K,
               const __half* __restrict__ V, __half* __restrict__ O)
{
    extern __shared__ __half smh[];
    __half* Qs = smh;
    __half* Ks = Qs + FQ_H;              // 2 buffers
    __half* Vs = Ks + 2 * FK_H;          // 2 buffers

    const int tid = threadIdx.x, wid = tid >> 5, lane = tid & 31;
    const int g = lane >> 2, tg = lane & 3;
    const int qt = (int)(gridDim.x - 1) - (int)blockIdx.x;   // heavy tiles first
    const int h = blockIdx.y, b = blockIdx.z;
    const int row0 = b * SEQ + qt * 128;
    const float scale = 0.08838834764831845f;
    const int lrA = lane & 15, lcA = (lane >> 4) << 3;
    const int lrB4 = (lane & 7) | ((lane >> 4) << 3);
    const int lcB4 = ((lane >> 3) & 1) << 3;
    // ldmatrix.trans per-lane offsets for V (natural [seq][hd] layout):
    // row (k) = (lane&7) + ((lane>>3)&1)*8 ; col (n) = (lane>>4)*8
    const int lrV = (lane & 7) | ((lane >> 3) & 1) << 3;
    const int lcV = (lane >> 4) << 3;

    auto issue_tile = [&](int jt) {
        const int kv0 = jt << 6;
        __half* Kb = Ks + (jt & 1) * FK_H;
        __half* Vb = Vs + (jt & 1) * FK_H;
#pragma unroll
        for (int i = 0; i < 4; i++) {           // K: 64 rows x 16 granules
            int idx = tid + i * 256;
            int row = idx >> 4, gc = (idx & 15) << 3;
            cpasync16(smem_addr(Kb + row * QSTRH + gc),
                      K + (size_t)(b * SEQ + kv0 + row) * DM + h * HD + gc);
        }
#pragma unroll
        for (int i = 0; i < 4; i++) {           // V: same natural layout
            int idx = tid + i * 256;
            int row = idx >> 4, gc = (idx & 15) << 3;
            cpasync16(smem_addr(Vb + row * QSTRH + gc),
                      V + (size_t)(b * SEQ + kv0 + row) * DM + h * HD + gc);
        }
    };

    // Q tile: 128 rows x 16 granules = 2048
#pragma unroll
    for (int i = 0; i < 8; i++) {
        int idx = tid + i * 256;
        int row = idx >> 4, gc = (idx & 15) << 3;
        cpasync16(smem_addr(Qs + row * QSTRH + gc),
                  Q + (size_t)(row0 + row) * DM + h * HD + gc);
    }
    CP_COMMIT;
    issue_tile(0);
    CP_COMMIT;

    float o[16][4];
#pragma unroll
    for (int nt = 0; nt < 16; nt++)
#pragma unroll
        for (int j = 0; j < 4; j++) o[nt][j] = 0.f;
    float mrun0 = -INFINITY, mrun1 = -INFINITY, l0 = 0.f, l1 = 0.f;

    const int ntiles = 2 * qt + 2;
    const int qr0 = qt * 128 + wid * 16 + g;
    const int qr1 = qr0 + 8;

    for (int jt = 0; jt < ntiles; jt++) {
        const int kv0 = jt << 6;
        __syncthreads();                       // all warps done with buffer being refilled
        bool pf = (jt + 1 < ntiles);
        if (pf) issue_tile(jt + 1);
        CP_COMMIT;
        if (pf) { CP_WAIT1; } else { CP_WAIT0; }
        __syncthreads();

        const __half* Kb = Ks + (jt & 1) * FK_H;
        const __half* Vb = Vs + (jt & 1) * FK_H;

        // ---- S = Q @ K^T : this warp's 16 q rows x 64 kv
        float sc[8][4];
#pragma unroll
        for (int nt = 0; nt < 8; nt++)
#pragma unroll
            for (int j = 0; j < 4; j++) sc[nt][j] = 0.f;

#pragma unroll
        for (int ks = 0; ks < 8; ks++) {
            const int kk = ks * 16;
            uint32_t a[4], bf[4][4];
            ldsm4(a, smem_addr(Qs + (wid * 16 + lrA) * QSTRH + kk + lcA));
#pragma unroll
            for (int nt2 = 0; nt2 < 4; nt2++)
                ldsm4(bf[nt2], smem_addr(Kb + (nt2 * 16 + lrB4) * QSTRH + kk + lcB4));
#pragma unroll
            for (int nt2 = 0; nt2 < 4; nt2++) {
                mma16(sc[nt2 * 2 + 0], a, bf[nt2] + 0);
                mma16(sc[nt2 * 2 + 1], a, bf[nt2] + 2);
            }
        }

        // ---- scale + causal mask
        const bool need_mask = (jt >= 2 * qt);
#pragma unroll
        for (int nt = 0; nt < 8; nt++) {
            int kc = kv0 + nt * 8 + 2 * tg;
#pragma unroll
            for (int j = 0; j < 4; j++) {
                float s = sc[nt][j] * scale;
                if (need_mask) {
                    int qr = (j >= 2) ? qr1 : qr0;
                    if (kc + (j & 1) > qr) s = -1e30f;
                }
                sc[nt][j] = s;
            }
        }

        // ---- in-warp online softmax (rows g and g+8 of this warp's block)
        float mx0 = -INFINITY, mx1 = -INFINITY;
#pragma unroll
        for (int nt = 0; nt < 8; nt++) {
            mx0 = fmaxf(mx0, fmaxf(sc[nt][0], sc[nt][1]));
            mx1 = fmaxf(mx1, fmaxf(sc[nt][2], sc[nt][3]));
        }
        mx0 = fmaxf(mx0, __shfl_xor_sync(0xffffffffu, mx0, 1));
        mx0 = fmaxf(mx0, __shfl_xor_sync(0xffffffffu, mx0, 2));
        mx1 = fmaxf(mx1, __shfl_xor_sync(0xffffffffu, mx1, 1));
        mx1 = fmaxf(mx1, __shfl_xor_sync(0xffffffffu, mx1, 2));
        float mn0 = fmaxf(mrun0, mx0), mn1 = fmaxf(mrun1, mx1);
        float fac0 = __expf(mrun0 - mn0), fac1 = __expf(mrun1 - mn1);
        mrun0 = mn0; mrun1 = mn1;

        float s0 = 0.f, s1 = 0.f;
#pragma unroll
        for (int nt = 0; nt < 8; nt++) {
            sc[nt][0] = __expf(sc[nt][0] - mn0);
            sc[nt][1] = __expf(sc[nt][1] - mn0);
            sc[nt][2] = __expf(sc[nt][2] - mn1);
            sc[nt][3] = __expf(sc[nt][3] - mn1);
            s0 += sc[nt][0] + sc[nt][1];
            s1 += sc[nt][2] + sc[nt][3];
        }
        s0 += __shfl_xor_sync(0xffffffffu, s0, 1);
        s0 += __shfl_xor_sync(0xffffffffu, s0, 2);
        s1 += __shfl_xor_sync(0xffffffffu, s1, 1);
        s1 += __shfl_xor_sync(0xffffffffu, s1, 2);
        l0 = l0 * fac0 + s0;
        l1 = l1 * fac1 + s1;

#pragma unroll
        for (int nt = 0; nt < 16; nt++) {
            o[nt][0] *= fac0; o[nt][1] *= fac0;
            o[nt][2] *= fac1; o[nt][3] *= fac1;
        }

        // ---- O += P @ V ; P packed from sc regs; V B-frags via ldmatrix.trans
#pragma unroll
        for (int kb = 0; kb < 4; kb++) {
            uint32_t a[4];
            a[0] = packh2(sc[2 * kb][0],     sc[2 * kb][1]);
            a[1] = packh2(sc[2 * kb][2],     sc[2 * kb][3]);
            a[2] = packh2(sc[2 * kb + 1][0], sc[2 * kb + 1][1]);
            a[3] = packh2(sc[2 * kb + 1][2], sc[2 * kb + 1][3]);
            const int kk = kb * 16;
#pragma unroll
            for (int nt2 = 0; nt2 < 8; nt2++) {
                uint32_t bf[4];
                ldsm4t(bf, smem_addr(Vb + (kk + lrV) * QSTRH + nt2 * 16 + lcV));
                mma16(o[nt2 * 2 + 0], a, bf + 0);
                mma16(o[nt2 * 2 + 1], a, bf + 2);
            }
        }
    }

    // ---- epilogue
    float inv0 = 1.0f / l0, inv1 = 1.0f / l1;
    int row = row0 + wid * 16 + g;
#pragma unroll
    for (int nt = 0; nt < 16; nt++) {
        int col = h * HD + nt * 8 + 2 * tg;
        *(__half2*)&O[(size_t)row * DM + col] =
            __floats2half2_rn(o[nt][0] * inv0, o[nt][1] * inv0);
        *(__half2*)&O[(size_t)(row + 8) * DM + col] =
            __floats2half2_rn(o[nt][2] * inv1, o[nt][3] * inv1);
    }
}

// ---------------- small kernels ----------------
__global__ __launch_bounds__(256) void cvtx_kernel(const float* __restrict__ x,
                                                   __half* __restrict__ y, int n4)
{
    int i = blockIdx.x * 256 + threadIdx.x;
    if (i >= n4) return;
    float4 v = ((const float4*)x)[i];
    ((__half2*)y)[2 * i]     = __floats2half2_rn(v.x, v.y);
    ((__half2*)y)[2 * i + 1] = __floats2half2_rn(v.z, v.w);
}

// src float: transpose [r,c] -> dst half [c,r]
__global__ __launch_bounds__(256) void trans_cvt(const float* __restrict__ src,
                                                 __half* __restrict__ dst, int R, int C)
{
    __shared__ float t[32][33];
    int c0 = blockIdx.x * 32, r0 = blockIdx.y * 32;
    int tx = threadIdx.x & 31, ty = threadIdx.x >> 5;
#pragma unroll
    for (int i = 0; i < 4; i++)
        t[ty + i * 8][tx] = src[(size_t)(r0 + ty + i * 8) * C + c0 + tx];
    __syncthreads();
#pragma unroll
    for (int i = 0; i < 4; i++)
        dst[(size_t)(c0 + ty + i * 8) * R + r0 + tx] = __float2half_rn(t[tx][ty + i * 8]);
}

__global__ __launch_bounds__(256) void rmsnorm_kernel(__half* __restrict__ x,
                                                      const float* __restrict__ w)
{
    const int row = blockIdx.x;
    __half* p = x + (size_t)row * LORA;
    const int t = threadIdx.x;
    float v0 = __half2float(p[t]), v1 = __half2float(p[t + 256]);
    float ss = v0 * v0 + v1 * v1;
#pragma unroll
    for (int o = 16; o; o >>= 1) ss += __shfl_xor_sync(0xffffffffu, ss, o);
    __shared__ float sred[8];
    if ((t & 31) == 0) sred[t >> 5] = ss;
    __syncthreads();
    float tot = 0.f;
#pragma unroll
    for (int i = 0; i < 8; i++) tot += sred[i];
    float inv = rsqrtf(tot * (1.0f / (float)LORA) + 1e-6f);
    p[t]       = __float2half_rn(v0 * inv * w[t]);
    p[t + 256] = __float2half_rn(v1 * inv * w[t + 256]);
}

// ---------------- launch ----------------
extern "C" void kernel_launch(void* const* d_in, const int* in_sizes, int n_in,
                              void* d_out, int out_size)
{
    const float* x     = (const float*)d_in[0];
    const float* fcos  = (const float*)d_in[1];
    const float* fsin  = (const float*)d_in[2];
    const float* w_kvc = (const float*)d_in[3];
    const float* kvw   = (const float*)d_in[4];
    const float* w_k   = (const float*)d_in[5];
    const float* w_v   = (const float*)d_in[6];
    const float* w_q   = (const float*)d_in[7];
    const float* w_o   = (const float*)d_in[8];
    float* out = (float*)d_out;

    __half *xh, *kvl, *Kb, *Vb, *Qb, *Ab;
    __half *wkvcT, *wkT, *wvT, *wqT, *woT;
    cudaGetSymbolAddress((void**)&xh, g_xh);
    cudaGetSymbolAddress((void**)&kvl, g_kvlat);
    cudaGetSymbolAddress((void**)&Kb, g_k);
    cudaGetSymbolAddress((void**)&Vb, g_v);
    cudaGetSymbolAddress((void**)&Qb, g_q);
    cudaGetSymbolAddress((void**)&Ab, g_attn);
    cudaGetSymbolAddress((void**)&wkvcT, g_wkvcT);
    cudaGetSymbolAddress((void**)&wkT, g_wkT);
    cudaGetSymbolAddress((void**)&wvT, g_wvT);
    cudaGetSymbolAddress((void**)&wqT, g_wqT);
    cudaGetSymbolAddress((void**)&woT, g_woT);

    cudaFuncSetAttribute((void*)gemm_f16<__half, false>, cudaFuncAttributeMaxDynamicSharedMemorySize, GEMM_SMEM);
    cudaFuncSetAttribute((void*)gemm_f16<__half, true>,  cudaFuncAttributeMaxDynamicSharedMemorySize, GEMM_SMEM);
    cudaFuncSetAttribute((void*)gemm_f16<float, false>,  cudaFuncAttributeMaxDynamicSharedMemorySize, GEMM_SMEM);
    cudaFuncSetAttribute((void*)flash_f16, cudaFuncAttributeMaxDynamicSharedMemorySize, FLASH_SMEM);

    // 1) x -> fp16
    cvtx_kernel<<<(ROWS * DM / 4 + 255) / 256, 256>>>(x, xh, ROWS * DM / 4);
    // 2-3) weights needed for q-GEMM
    trans_cvt<<<dim3(DM / 32, DM / 32), 256>>>(w_q, wqT, DM, DM);
    trans_cvt<<<dim3(LORA / 32, DM / 32), 256>>>(w_kvc, wkvcT, DM, LORA);
    // 4) q = rope(x @ w_q)  <-- ncu-profiled slot
    gemm_f16<__half, true><<<dim3(DM / 128, ROWS / 128), 256, GEMM_SMEM>>>(
        xh, wqT, Qb, ROWS, DM, DM, fcos, fsin);
    // 5-7) remaining weight transposes
    trans_cvt<<<dim3(DM / 32, LORA / 32), 256>>>(w_k, wkT, LORA, DM);
    trans_cvt<<<dim3(DM / 32, LORA / 32), 256>>>(w_v, wvT, LORA, DM);
    trans_cvt<<<dim3(DM / 32, DM / 32), 256>>>(w_o, woT, DM, DM);
    // 8) kv_compressed = x @ w_kvc  [4096, 512]
    gemm_f16<__half, false><<<dim3(LORA / 128, ROWS / 128), 256, GEMM_SMEM>>>(
        xh, wkvcT, kvl, ROWS, LORA, DM, nullptr, nullptr);
    // 9) rmsnorm in place (fp32 stats)
    rmsnorm_kernel<<<ROWS, 256>>>(kvl, kvw);
    // 10) k = rope(kv_latent @ w_k_up)
    gemm_f16<__half, true><<<dim3(DM / 128, ROWS / 128), 256, GEMM_SMEM>>>(
        kvl, wkT, Kb, ROWS, DM, LORA, fcos, fsin);
    // 11) v = kv_latent @ w_v_up
    gemm_f16<__half, false><<<dim3(DM / 128, ROWS / 128), 256, GEMM_SMEM>>>(
        kvl, wvT, Vb, ROWS, DM, LORA, nullptr, nullptr);
    // 12) flash attention (V in natural layout)
    flash_f16<<<dim3(SEQ / 128, NH, BATCH), 256, FLASH_SMEM>>>(Qb, Kb, Vb, Ab);
    // 13) out = attn @ w_out (fp32 output)
    gemm_f16<float, false><<<dim3(DM / 128, ROWS / 128), 256, GEMM_SMEM>>>(
        Ab, woT, out, ROWS, DM, DM, nullptr, nullptr);
}

// round 9
// speedup vs baseline: 2.4810x; 1.0492x over previous
#include <cuda_runtime.h>
#include <cuda_fp16.h>
#include <cstdint>
#include <math.h>

// ---------------- constants ----------------
#define DM 2048
#define NH 16
#define HD 128
#define LORA 512
#define SEQ 2048
#define BATCH 2
#define ROWS (BATCH*SEQ)   // 4096

// ---------------- scratch (fp16 operands, fp32 accum everywhere) ----------------
__device__ __half g_xh[ROWS * DM];
__device__ __half g_kvlat[ROWS * LORA];
__device__ __half g_k[ROWS * DM];
__device__ __half g_v[ROWS * DM];
__device__ __half g_q[ROWS * DM];
__device__ __half g_attn[ROWS * DM];
__device__ __half g_wkvcT[LORA * DM];
__device__ __half g_wkT[DM * LORA];
__device__ __half g_wvT[DM * LORA];
__device__ __half g_wqT[DM * DM];
__device__ __half g_woT[DM * DM];

// ---------------- helpers ----------------
__device__ __forceinline__ uint32_t smem_addr(const void* p) {
    return (uint32_t)__cvta_generic_to_shared(p);
}
__device__ __forceinline__ void cpasync16(uint32_t s, const void* g) {
    asm volatile("cp.async.cg.shared.global [%0], [%1], 16;" :: "r"(s), "l"(g));
}
#define CP_COMMIT asm volatile("cp.async.commit_group;" ::: "memory")
#define CP_WAIT0  asm volatile("cp.async.wait_group 0;" ::: "memory")
#define CP_WAIT1  asm volatile("cp.async.wait_group 1;" ::: "memory")

// mma.sync m16n8k16 fp16 in, fp32 accum: D += A@B ; A row-major, B col-major
__device__ __forceinline__ void mma16(float* c, const uint32_t* a, const uint32_t* b) {
    asm volatile(
        "mma.sync.aligned.m16n8k16.row.col.f32.f16.f16.f32 "
        "{%0,%1,%2,%3}, {%4,%5,%6,%7}, {%8,%9}, {%0,%1,%2,%3};"
        : "+f"(c[0]), "+f"(c[1]), "+f"(c[2]), "+f"(c[3])
        : "r"(a[0]), "r"(a[1]), "r"(a[2]), "r"(a[3]), "r"(b[0]), "r"(b[1]));
}
__device__ __forceinline__ void ldsm4(uint32_t* r, uint32_t addr) {
    asm volatile("ldmatrix.sync.aligned.m8n8.x4.shared.b16 {%0,%1,%2,%3}, [%4];"
        : "=r"(r[0]), "=r"(r[1]), "=r"(r[2]), "=r"(r[3]) : "r"(addr));
}
__device__ __forceinline__ void ldsm4t(uint32_t* r, uint32_t addr) {
    asm volatile("ldmatrix.sync.aligned.m8n8.x4.trans.shared.b16 {%0,%1,%2,%3}, [%4];"
        : "=r"(r[0]), "=r"(r[1]), "=r"(r[2]), "=r"(r[3]) : "r"(addr));
}
__device__ __forceinline__ uint32_t packh2(float lo, float hi) {
    __half2 h = __floats2half2_rn(lo, hi);
    return *(uint32_t*)&h;
}

// ================= fp16 mma.sync GEMM =================
// C[M,N] = A[M,K] @ Bt[N,K]^T ; CTA 128x128, BK=64, 8 warps (warp 64x32).
// 2-stage pipeline, 72KB smem -> 2 CTAs/SM.
// Runtime fused-RoPE epilogue (fc != nullptr) and optional second (Bt2, C2)
// problem sharing the same A: blocks with blockIdx.x >= nsplit compute
// C2 = A @ Bt2^T (no rope). Used to merge the k-up and v-up projections.
#define GSTAGES 2
#define GSTRH 72                       // halfs per row (64 + 8 pad)
#define GSTAGE_H (128*GSTRH*2)         // A + B halfs per stage
#define GEMM_SMEM (GSTAGES*GSTAGE_H*2) // 73728 B

template<typename CT>
__global__ __launch_bounds__(256, 2)
void gemm_f16(const __half* __restrict__ A, const __half* __restrict__ Bt0,
              CT* __restrict__ C0, int M, int N, int K,
              const float* __restrict__ fc, const float* __restrict__ fs,
              const __half* __restrict__ Bt2, CT* __restrict__ C2, int nsplit)
{
    extern __shared__ __half smh[];
    const int tid = threadIdx.x, wid = tid >> 5, lane = tid & 31;
    const int g = lane >> 2, tg = lane & 3;
    const int wm = wid >> 2, wn = wid & 3;     // 2 x 4 warp grid, warp = 64x32
    int bx = blockIdx.x;
    const __half* Bt = Bt0;
    CT* C = C0;
    bool rope = (fc != nullptr);
    if (Bt2 != nullptr && bx >= nsplit) { Bt = Bt2; C = C2; bx -= nsplit; rope = false; }
    const int m0 = blockIdx.y * 128, n0 = bx * 128;
    const int NC = K >> 6;
    const int lrA = lane & 15, lcA = (lane >> 4) << 3;
    const int lrB4 = (lane & 7) | ((lane >> 4) << 3);
    const int lcB4 = ((lane >> 3) & 1) << 3;

    float c[4][4][4];
#pragma unroll
    for (int mt = 0; mt < 4; mt++)
#pragma unroll
        for (int nt = 0; nt < 4; nt++)
#pragma unroll
            for (int j = 0; j < 4; j++) c[mt][nt][j] = 0.f;

    auto load_chunk = [&](int stage, int ch) {
        __half* As = smh + stage * GSTAGE_H;
        __half* Bs = As + 128 * GSTRH;
        const __half* Ag = A + (size_t)m0 * K + ch * 64;
        const __half* Bg = Bt + (size_t)n0 * K + ch * 64;
#pragma unroll
        for (int i = 0; i < 4; i++) {
            int idx = tid + i * 256;               // 1024 granules of 8 halfs
            int row = idx >> 3, gc = (idx & 7) << 3;
            cpasync16(smem_addr(As + row * GSTRH + gc), Ag + (size_t)row * K + gc);
        }
#pragma unroll
        for (int i = 0; i < 4; i++) {
            int idx = tid + i * 256;
            int row = idx >> 3, gc = (idx & 7) << 3;
            cpasync16(smem_addr(Bs + row * GSTRH + gc), Bg + (size_t)row * K + gc);
        }
    };

    load_chunk(0, 0);
    CP_COMMIT;

    for (int ch = 0; ch < NC; ch++) {
        int pf = ch + 1;
        if (pf < NC) { load_chunk(pf & 1, pf); CP_COMMIT; CP_WAIT1; }
        else         { CP_WAIT0; }
        __syncthreads();

        const __half* As = smh + (ch & 1) * GSTAGE_H;
        const __half* Bs = As + 128 * GSTRH;
#pragma unroll
        for (int ks = 0; ks < 4; ks++) {
            const int kk = ks * 16;
            uint32_t a[4][4], b[2][4];
#pragma unroll
            for (int mt = 0; mt < 4; mt++)
                ldsm4(a[mt], smem_addr(As + (wm * 64 + mt * 16 + lrA) * GSTRH + kk + lcA));
#pragma unroll
            for (int nt2 = 0; nt2 < 2; nt2++)
                ldsm4(b[nt2], smem_addr(Bs + (wn * 32 + nt2 * 16 + lrB4) * GSTRH + kk + lcB4));
#pragma unroll
            for (int mt = 0; mt < 4; mt++)
#pragma unroll
                for (int nt2 = 0; nt2 < 2; nt2++) {
                    mma16(c[mt][nt2 * 2 + 0], a[mt], b[nt2] + 0);
                    mma16(c[mt][nt2 * 2 + 1], a[mt], b[nt2] + 2);
                }
        }
        __syncthreads();   // all reads of this stage done before it is refilled
    }

    // epilogue (+ optional fused RoPE on fp32 accumulators)
#pragma unroll
    for (int mt = 0; mt < 4; mt++) {
        int row = m0 + wm * 64 + mt * 16 + g;
#pragma unroll
        for (int nt = 0; nt < 4; nt++) {
            int col = n0 + wn * 32 + nt * 8 + 2 * tg;
            float v0 = c[mt][nt][0], v1 = c[mt][nt][1];
            float v2 = c[mt][nt][2], v3 = c[mt][nt][3];
            if (rope) {
                int p = (col & 127) >> 1;
                int s0 = row & (SEQ - 1);
                int s1 = (row + 8) & (SEQ - 1);
                float c0 = fc[s0 * 64 + p], n0v = fs[s0 * 64 + p];
                float c1 = fc[s1 * 64 + p], n1v = fs[s1 * 64 + p];
                float t0 = v0 * c0 - v1 * n0v, t1 = v0 * n0v + v1 * c0;
                float t2 = v2 * c1 - v3 * n1v, t3 = v2 * n1v + v3 * c1;
                v0 = t0; v1 = t1; v2 = t2; v3 = t3;
            }
            if constexpr (sizeof(CT) == 2) {
                *(__half2*)&C[(size_t)row * N + col] = __floats2half2_rn(v0, v1);
                *(__half2*)&C[(size_t)(row + 8) * N + col] = __floats2half2_rn(v2, v3);
            } else {
                *(float2*)&C[(size_t)row * N + col] = make_float2(v0, v1);
                *(float2*)&C[(size_t)(row + 8) * N + col] = make_float2(v2, v3);
            }
        }
    }
}

// ================= flash attention (causal), fp16 mma.sync =================
// BM=128 q, BN=64 kv. 8 warps, each owns 16 q rows x full 64 kv. P stays in regs.
// K and V both loaded in natural [seq][hd] layout (V B-frags via ldmatrix.trans).
// K/V tiles double-buffered; Q loaded once.
#define QSTRH 136                       // 128 + 8 pad
#define FQ_H (128*QSTRH)
#define FK_H (64*QSTRH)
#define FLASH_SMEM ((FQ_H + 4*FK_H) * 2)

__global__ __launch_bounds__(256, 1)
void flash_f16(const __half* __restrict__ Q, const __half* __restrict__ K,
               const __half* __restrict__ V, __half* __restrict__ O)
{
    extern __shared__ __half smh[];
    __half* Qs = smh;
    __half* Ks = Qs + FQ_H;              // 2 buffers
    __half* Vs = Ks + 2 * FK_H;          // 2 buffers

    const int tid = threadIdx.x, wid = tid >> 5, lane = tid & 31;
    const int g = lane >> 2, tg = lane & 3;
    const int qt = (int)(gridDim.x - 1) - (int)blockIdx.x;   // heavy tiles first
    const int h = blockIdx.y, b = blockIdx.z;
    const int row0 = b * SEQ + qt * 128;
    const float scale = 0.08838834764831845f;
    const int lrA = lane & 15, lcA = (lane >> 4) << 3;
    const int lrB4 = (lane & 7) | ((lane >> 4) << 3);
    const int lcB4 = ((lane >> 3) & 1) << 3;
    // ldmatrix.trans per-lane offsets for V (natural [seq][hd] layout)
    const int lrV = (lane & 7) | ((lane >> 3) & 1) << 3;
    const int lcV = (lane >> 4) << 3;

    auto issue_tile = [&](int jt) {
        const int kv0 = jt << 6;
        __half* Kb = Ks + (jt & 1) * FK_H;
        __half* Vb = Vs + (jt & 1) * FK_H;
#pragma unroll
        for (int i = 0; i < 4; i++) {           // K: 64 rows x 16 granules
            int idx = tid + i * 256;
            int row = idx >> 4, gc = (idx & 15) << 3;
            cpasync16(smem_addr(Kb + row * QSTRH + gc),
                      K + (size_t)(b * SEQ + kv0 + row) * DM + h * HD + gc);
        }
#pragma unroll
        for (int i = 0; i < 4; i++) {           // V: same natural layout
            int idx = tid + i * 256;
            int row = idx >> 4, gc = (idx & 15) << 3;
            cpasync16(smem_addr(Vb + row * QSTRH + gc),
                      V + (size_t)(b * SEQ + kv0 + row) * DM + h * HD + gc);
        }
    };

    // Q tile: 128 rows x 16 granules = 2048
#pragma unroll
    for (int i = 0; i < 8; i++) {
        int idx = tid + i * 256;
        int row = idx >> 4, gc = (idx & 15) << 3;
        cpasync16(smem_addr(Qs + row * QSTRH + gc),
                  Q + (size_t)(row0 + row) * DM + h * HD + gc);
    }
    CP_COMMIT;
    issue_tile(0);
    CP_COMMIT;

    float o[16][4];
#pragma unroll
    for (int nt = 0; nt < 16; nt++)
#pragma unroll
        for (int j = 0; j < 4; j++) o[nt][j] = 0.f;
    float mrun0 = -INFINITY, mrun1 = -INFINITY, l0 = 0.f, l1 = 0.f;

    const int ntiles = 2 * qt + 2;
    const int qr0 = qt * 128 + wid * 16 + g;
    const int qr1 = qr0 + 8;

    for (int jt = 0; jt < ntiles; jt++) {
        const int kv0 = jt << 6;
        __syncthreads();                       // all warps done with buffer being refilled
        bool pf = (jt + 1 < ntiles);
        if (pf) issue_tile(jt + 1);
        CP_COMMIT;
        if (pf) { CP_WAIT1; } else { CP_WAIT0; }
        __syncthreads();

        const __half* Kb = Ks + (jt & 1) * FK_H;
        const __half* Vb = Vs + (jt & 1) * FK_H;

        // ---- S = Q @ K^T : this warp's 16 q rows x 64 kv
        float sc[8][4];
#pragma unroll
        for (int nt = 0; nt < 8; nt++)
#pragma unroll
            for (int j = 0; j < 4; j++) sc[nt][j] = 0.f;

#pragma unroll
        for (int ks = 0; ks < 8; ks++) {
            const int kk = ks * 16;
            uint32_t a[4], bf[4][4];
            ldsm4(a, smem_addr(Qs + (wid * 16 + lrA) * QSTRH + kk + lcA));
#pragma unroll
            for (int nt2 = 0; nt2 < 4; nt2++)
                ldsm4(bf[nt2], smem_addr(Kb + (nt2 * 16 + lrB4) * QSTRH + kk + lcB4));
#pragma unroll
            for (int nt2 = 0; nt2 < 4; nt2++) {
                mma16(sc[nt2 * 2 + 0], a, bf[nt2] + 0);
                mma16(sc[nt2 * 2 + 1], a, bf[nt2] + 2);
            }
        }

        // ---- scale + causal mask
        const bool need_mask = (jt >= 2 * qt);
#pragma unroll
        for (int nt = 0; nt < 8; nt++) {
            int kc = kv0 + nt * 8 + 2 * tg;
#pragma unroll
            for (int j = 0; j < 4; j++) {
                float s = sc[nt][j] * scale;
                if (need_mask) {
                    int qr = (j >= 2) ? qr1 : qr0;
                    if (kc + (j & 1) > qr) s = -1e30f;
                }
                sc[nt][j] = s;
            }
        }

        // ---- in-warp online softmax (rows g and g+8 of this warp's block)
        float mx0 = -INFINITY, mx1 = -INFINITY;
#pragma unroll
        for (int nt = 0; nt < 8; nt++) {
            mx0 = fmaxf(mx0, fmaxf(sc[nt][0], sc[nt][1]));
            mx1 = fmaxf(mx1, fmaxf(sc[nt][2], sc[nt][3]));
        }
        mx0 = fmaxf(mx0, __shfl_xor_sync(0xffffffffu, mx0, 1));
        mx0 = fmaxf(mx0, __shfl_xor_sync(0xffffffffu, mx0, 2));
        mx1 = fmaxf(mx1, __shfl_xor_sync(0xffffffffu, mx1, 1));
        mx1 = fmaxf(mx1, __shfl_xor_sync(0xffffffffu, mx1, 2));
        float mn0 = fmaxf(mrun0, mx0), mn1 = fmaxf(mrun1, mx1);
        float fac0 = __expf(mrun0 - mn0), fac1 = __expf(mrun1 - mn1);
        mrun0 = mn0; mrun1 = mn1;

        float s0 = 0.f, s1 = 0.f;
#pragma unroll
        for (int nt = 0; nt < 8; nt++) {
            sc[nt][0] = __expf(sc[nt][0] - mn0);
            sc[nt][1] = __expf(sc[nt][1] - mn0);
            sc[nt][2] = __expf(sc[nt][2] - mn1);
            sc[nt][3] = __expf(sc[nt][3] - mn1);
            s0 += sc[nt][0] + sc[nt][1];
            s1 += sc[nt][2] + sc[nt][3];
        }
        s0 += __shfl_xor_sync(0xffffffffu, s0, 1);
        s0 += __shfl_xor_sync(0xffffffffu, s0, 2);
        s1 += __shfl_xor_sync(0xffffffffu, s1, 1);
        s1 += __shfl_xor_sync(0xffffffffu, s1, 2);
        l0 = l0 * fac0 + s0;
        l1 = l1 * fac1 + s1;

#pragma unroll
        for (int nt = 0; nt < 16; nt++) {
            o[nt][0] *= fac0; o[nt][1] *= fac0;
            o[nt][2] *= fac1; o[nt][3] *= fac1;
        }

        // ---- O += P @ V ; P packed from sc regs; V B-frags via ldmatrix.trans
#pragma unroll
        for (int kb = 0; kb < 4; kb++) {
            uint32_t a[4];
            a[0] = packh2(sc[2 * kb][0],     sc[2 * kb][1]);
            a[1] = packh2(sc[2 * kb][2],     sc[2 * kb][3]);
            a[2] = packh2(sc[2 * kb + 1][0], sc[2 * kb + 1][1]);
            a[3] = packh2(sc[2 * kb + 1][2], sc[2 * kb + 1][3]);
            const int kk = kb * 16;
#pragma unroll
            for (int nt2 = 0; nt2 < 8; nt2++) {
                uint32_t bf[4];
                ldsm4t(bf, smem_addr(Vb + (kk + lrV) * QSTRH + nt2 * 16 + lcV));
                mma16(o[nt2 * 2 + 0], a, bf + 0);
                mma16(o[nt2 * 2 + 1], a, bf + 2);
            }
        }
    }

    // ---- epilogue
    float inv0 = 1.0f / l0, inv1 = 1.0f / l1;
    int row = row0 + wid * 16 + g;
#pragma unroll
    for (int nt = 0; nt < 16; nt++) {
        int col = h * HD + nt * 8 + 2 * tg;
        *(__half2*)&O[(size_t)row * DM + col] =
            __floats2half2_rn(o[nt][0] * inv0, o[nt][1] * inv0);
        *(__half2*)&O[(size_t)(row + 8) * DM + col] =
            __floats2half2_rn(o[nt][2] * inv1, o[nt][3] * inv1);
    }
}

// ---------------- small kernels ----------------
__global__ __launch_bounds__(256) void cvtx_kernel(const float* __restrict__ x,
                                                   __half* __restrict__ y, int n4)
{
    int i = blockIdx.x * 256 + threadIdx.x;
    if (i >= n4) return;
    float4 v = ((const float4*)x)[i];
    ((__half2*)y)[2 * i]     = __floats2half2_rn(v.x, v.y);
    ((__half2*)y)[2 * i + 1] = __floats2half2_rn(v.z, v.w);
}

// src float: transpose [r,c] -> dst half [c,r]
__global__ __launch_bounds__(256) void trans_cvt(const float* __restrict__ src,
                                                 __half* __restrict__ dst, int R, int C)
{
    __shared__ float t[32][33];
    int c0 = blockIdx.x * 32, r0 = blockIdx.y * 32;
    int tx = threadIdx.x & 31, ty = threadIdx.x >> 5;
#pragma unroll
    for (int i = 0; i < 4; i++)
        t[ty + i * 8][tx] = src[(size_t)(r0 + ty + i * 8) * C + c0 + tx];
    __syncthreads();
#pragma unroll
    for (int i = 0; i < 4; i++)
        dst[(size_t)(c0 + ty + i * 8) * R + r0 + tx] = __float2half_rn(t[tx][ty + i * 8]);
}

__global__ __launch_bounds__(256) void rmsnorm_kernel(__half* __restrict__ x,
                                                      const float* __restrict__ w)
{
    const int row = blockIdx.x;
    __half* p = x + (size_t)row * LORA;
    const int t = threadIdx.x;
    float v0 = __half2float(p[t]), v1 = __half2float(p[t + 256]);
    float ss = v0 * v0 + v1 * v1;
#pragma unroll
    for (int o = 16; o; o >>= 1) ss += __shfl_xor_sync(0xffffffffu, ss, o);
    __shared__ float sred[8];
    if ((t & 31) == 0) sred[t >> 5] = ss;
    __syncthreads();
    float tot = 0.f;
#pragma unroll
    for (int i = 0; i < 8; i++) tot += sred[i];
    float inv = rsqrtf(tot * (1.0f / (float)LORA) + 1e-6f);
    p[t]       = __float2half_rn(v0 * inv * w[t]);
    p[t + 256] = __float2half_rn(v1 * inv * w[t + 256]);
}

// ---------------- launch ----------------
extern "C" void kernel_launch(void* const* d_in, const int* in_sizes, int n_in,
                              void* d_out, int out_size)
{
    const float* x     = (const float*)d_in[0];
    const float* fcos  = (const float*)d_in[1];
    const float* fsin  = (const float*)d_in[2];
    const float* w_kvc = (const float*)d_in[3];
    const float* kvw   = (const float*)d_in[4];
    const float* w_k   = (const float*)d_in[5];
    const float* w_v   = (const float*)d_in[6];
    const float* w_q   = (const float*)d_in[7];
    const float* w_o   = (const float*)d_in[8];
    float* out = (float*)d_out;

    __half *xh, *kvl, *Kb, *Vb, *Qb, *Ab;
    __half *wkvcT, *wkT, *wvT, *wqT, *woT;
    cudaGetSymbolAddress((void**)&xh, g_xh);
    cudaGetSymbolAddress((void**)&kvl, g_kvlat);
    cudaGetSymbolAddress((void**)&Kb, g_k);
    cudaGetSymbolAddress((void**)&Vb, g_v);
    cudaGetSymbolAddress((void**)&Qb, g_q);
    cudaGetSymbolAddress((void**)&Ab, g_attn);
    cudaGetSymbolAddress((void**)&wkvcT, g_wkvcT);
    cudaGetSymbolAddress((void**)&wkT, g_wkT);
    cudaGetSymbolAddress((void**)&wvT, g_wvT);
    cudaGetSymbolAddress((void**)&wqT, g_wqT);
    cudaGetSymbolAddress((void**)&woT, g_woT);

    cudaFuncSetAttribute((void*)gemm_f16<__half>, cudaFuncAttributeMaxDynamicSharedMemorySize, GEMM_SMEM);
    cudaFuncSetAttribute((void*)gemm_f16<float>,  cudaFuncAttributeMaxDynamicSharedMemorySize, GEMM_SMEM);
    cudaFuncSetAttribute((void*)flash_f16, cudaFuncAttributeMaxDynamicSharedMemorySize, FLASH_SMEM);

    // one-time side stream + events (host resources; every call does identical GPU work)
    static cudaStream_t s2 = nullptr;
    static cudaEvent_t ev_x = nullptr, ev_join = nullptr;
    if (s2 == nullptr) {
        cudaStreamCreateWithFlags(&s2, cudaStreamNonBlocking);
        cudaEventCreateWithFlags(&ev_x, cudaEventDisableTiming);
        cudaEventCreateWithFlags(&ev_join, cudaEventDisableTiming);
    }

    // ---- branch B (s2): w_q transpose (no deps) ----
    trans_cvt<<<dim3(DM / 32, DM / 32), 256, 0, s2>>>(w_q, wqT, DM, DM);

    // ---- main: x -> fp16, then signal s2 ----
    cvtx_kernel<<<(ROWS * DM / 4 + 255) / 256, 256>>>(x, xh, ROWS * DM / 4);
    cudaEventRecord(ev_x, 0);
    cudaStreamWaitEvent(s2, ev_x, 0);

    // ---- branch B (s2): q = rope(x @ w_q), then w_o transpose ----
    gemm_f16<__half><<<dim3(DM / 128, ROWS / 128), 256, GEMM_SMEM, s2>>>(
        xh, wqT, Qb, ROWS, DM, DM, fcos, fsin, nullptr, nullptr, 0);
    trans_cvt<<<dim3(DM / 32, DM / 32), 256, 0, s2>>>(w_o, woT, DM, DM);
    cudaEventRecord(ev_join, s2);

    // ---- branch A (main): kv chain ----
    trans_cvt<<<dim3(LORA / 32, DM / 32), 256>>>(w_kvc, wkvcT, DM, LORA);
    gemm_f16<__half><<<dim3(LORA / 128, ROWS / 128), 256, GEMM_SMEM>>>(
        xh, wkvcT, kvl, ROWS, LORA, DM, nullptr, nullptr, nullptr, nullptr, 0);
    rmsnorm_kernel<<<ROWS, 256>>>(kvl, kvw);
    trans_cvt<<<dim3(DM / 32, LORA / 32), 256>>>(w_k, wkT, LORA, DM);
    trans_cvt<<<dim3(DM / 32, LORA / 32), 256>>>(w_v, wvT, LORA, DM);
    // merged k-up (rope) + v-up (no rope): one 1024-CTA launch
    gemm_f16<__half><<<dim3(2 * (DM / 128), ROWS / 128), 256, GEMM_SMEM>>>(
        kvl, wkT, Kb, ROWS, DM, LORA, fcos, fsin, wvT, Vb, DM / 128);

    // ---- join, then flash + output projection on main ----
    cudaStreamWaitEvent(0, ev_join, 0);
    flash_f16<<<dim3(SEQ / 128, NH, BATCH), 256, FLASH_SMEM>>>(Qb, Kb, Vb, Ab);
    gemm_f16<float><<<dim3(DM / 128, ROWS / 128), 256, GEMM_SMEM>>>(
        Ab, woT, out, ROWS, DM, DM, nullptr, nullptr, nullptr, nullptr, 0);
}

// round 10
// speedup vs baseline: 2.5342x; 1.0214x over previous
#include <cuda_runtime.h>
#include <cuda_fp16.h>
#include <cstdint>
#include <math.h>

// ---------------- constants ----------------
#define DM 2048
#define NH 16
#define HD 128
#define LORA 512
#define SEQ 2048
#define BATCH 2
#define ROWS (BATCH*SEQ)   // 4096

// ---------------- scratch (fp16 operands, fp32 accum everywhere) ----------------
__device__ __half g_xh[ROWS * DM];
__device__ __half g_kvlat[ROWS * LORA];
__device__ __half g_k[ROWS * DM];
__device__ __half g_v[ROWS * DM];
__device__ __half g_q[ROWS * DM];
__device__ __half g_attn[ROWS * DM];
__device__ __half g_wkvcT[LORA * DM];
__device__ __half g_wkT[DM * LORA];
__device__ __half g_wvT[DM * LORA];
__device__ __half g_wqT[DM * DM];
__device__ __half g_woT[DM * DM];

// ---------------- helpers ----------------
__device__ __forceinline__ uint32_t smem_addr(const void* p) {
    return (uint32_t)__cvta_generic_to_shared(p);
}
__device__ __forceinline__ void cpasync16(uint32_t s, const void* g) {
    asm volatile("cp.async.cg.shared.global [%0], [%1], 16;" :: "r"(s), "l"(g));
}
#define CP_COMMIT asm volatile("cp.async.commit_group;" ::: "memory")
#define CP_WAIT0  asm volatile("cp.async.wait_group 0;" ::: "memory")
#define CP_WAIT1  asm volatile("cp.async.wait_group 1;" ::: "memory")

// mma.sync m16n8k16 fp16 in, fp32 accum: D += A@B ; A row-major, B col-major
__device__ __forceinline__ void mma16(float* c, const uint32_t* a, const uint32_t* b) {
    asm volatile(
        "mma.sync.aligned.m16n8k16.row.col.f32.f16.f16.f32 "
        "{%0,%1,%2,%3}, {%4,%5,%6,%7}, {%8,%9}, {%0,%1,%2,%3};"
        : "+f"(c[0]), "+f"(c[1]), "+f"(c[2]), "+f"(c[3])
        : "r"(a[0]), "r"(a[1]), "r"(a[2]), "r"(a[3]), "r"(b[0]), "r"(b[1]));
}
__device__ __forceinline__ void ldsm4(uint32_t* r, uint32_t addr) {
    asm volatile("ldmatrix.sync.aligned.m8n8.x4.shared.b16 {%0,%1,%2,%3}, [%4];"
        : "=r"(r[0]), "=r"(r[1]), "=r"(r[2]), "=r"(r[3]) : "r"(addr));
}
__device__ __forceinline__ void ldsm4t(uint32_t* r, uint32_t addr) {
    asm volatile("ldmatrix.sync.aligned.m8n8.x4.trans.shared.b16 {%0,%1,%2,%3}, [%4];"
        : "=r"(r[0]), "=r"(r[1]), "=r"(r[2]), "=r"(r[3]) : "r"(addr));
}
__device__ __forceinline__ uint32_t packh2(float lo, float hi) {
    __half2 h = __floats2half2_rn(lo, hi);
    return *(uint32_t*)&h;
}

// ================= fp16 mma.sync GEMM =================
// C[M,N] = A[M,K] @ Bt[N,K]^T ; CTA 128x128, BK=64, 8 warps (warp 64x32).
// 2-stage pipeline, 72KB smem -> 2 CTAs/SM.
// Runtime fused-RoPE epilogue (fc != nullptr) and optional second (Bt2, C2)
// problem sharing the same A (k-up + v-up merge).
#define GSTAGES 2
#define GSTRH 72                       // halfs per row (64 + 8 pad)
#define GSTAGE_H (128*GSTRH*2)         // A + B halfs per stage
#define GEMM_SMEM (GSTAGES*GSTAGE_H*2) // 73728 B

template<typename CT>
__global__ __launch_bounds__(256, 2)
void gemm_f16(const __half* __restrict__ A, const __half* __restrict__ Bt0,
              CT* __restrict__ C0, int M, int N, int K,
              const float* __restrict__ fc, const float* __restrict__ fs,
              const __half* __restrict__ Bt2, CT* __restrict__ C2, int nsplit)
{
    extern __shared__ __half smh[];
    const int tid = threadIdx.x, wid = tid >> 5, lane = tid & 31;
    const int g = lane >> 2, tg = lane & 3;
    const int wm = wid >> 2, wn = wid & 3;     // 2 x 4 warp grid, warp = 64x32
    int bx = blockIdx.x;
    const __half* Bt = Bt0;
    CT* C = C0;
    bool rope = (fc != nullptr);
    if (Bt2 != nullptr && bx >= nsplit) { Bt = Bt2; C = C2; bx -= nsplit; rope = false; }
    const int m0 = blockIdx.y * 128, n0 = bx * 128;
    const int NC = K >> 6;
    const int lrA = lane & 15, lcA = (lane >> 4) << 3;
    const int lrB4 = (lane & 7) | ((lane >> 4) << 3);
    const int lcB4 = ((lane >> 3) & 1) << 3;

    float c[4][4][4];
#pragma unroll
    for (int mt = 0; mt < 4; mt++)
#pragma unroll
        for (int nt = 0; nt < 4; nt++)
#pragma unroll
            for (int j = 0; j < 4; j++) c[mt][nt][j] = 0.f;

    auto load_chunk = [&](int stage, int ch) {
        __half* As = smh + stage * GSTAGE_H;
        __half* Bs = As + 128 * GSTRH;
        const __half* Ag = A + (size_t)m0 * K + ch * 64;
        const __half* Bg = Bt + (size_t)n0 * K + ch * 64;
#pragma unroll
        for (int i = 0; i < 4; i++) {
            int idx = tid + i * 256;               // 1024 granules of 8 halfs
            int row = idx >> 3, gc = (idx & 7) << 3;
            cpasync16(smem_addr(As + row * GSTRH + gc), Ag + (size_t)row * K + gc);
        }
#pragma unroll
        for (int i = 0; i < 4; i++) {
            int idx = tid + i * 256;
            int row = idx >> 3, gc = (idx & 7) << 3;
            cpasync16(smem_addr(Bs + row * GSTRH + gc), Bg + (size_t)row * K + gc);
        }
    };

    load_chunk(0, 0);
    CP_COMMIT;

    for (int ch = 0; ch < NC; ch++) {
        int pf = ch + 1;
        if (pf < NC) { load_chunk(pf & 1, pf); CP_COMMIT; CP_WAIT1; }
        else         { CP_WAIT0; }
        __syncthreads();

        const __half* As = smh + (ch & 1) * GSTAGE_H;
        const __half* Bs = As + 128 * GSTRH;
#pragma unroll
        for (int ks = 0; ks < 4; ks++) {
            const int kk = ks * 16;
            uint32_t a[4][4], b[2][4];
#pragma unroll
            for (int mt = 0; mt < 4; mt++)
                ldsm4(a[mt], smem_addr(As + (wm * 64 + mt * 16 + lrA) * GSTRH + kk + lcA));
#pragma unroll
            for (int nt2 = 0; nt2 < 2; nt2++)
                ldsm4(b[nt2], smem_addr(Bs + (wn * 32 + nt2 * 16 + lrB4) * GSTRH + kk + lcB4));
#pragma unroll
            for (int mt = 0; mt < 4; mt++)
#pragma unroll
                for (int nt2 = 0; nt2 < 2; nt2++) {
                    mma16(c[mt][nt2 * 2 + 0], a[mt], b[nt2] + 0);
                    mma16(c[mt][nt2 * 2 + 1], a[mt], b[nt2] + 2);
                }
        }
        __syncthreads();   // all reads of this stage done before it is refilled
    }

    // epilogue (+ optional fused RoPE on fp32 accumulators)
#pragma unroll
    for (int mt = 0; mt < 4; mt++) {
        int row = m0 + wm * 64 + mt * 16 + g;
#pragma unroll
        for (int nt = 0; nt < 4; nt++) {
            int col = n0 + wn * 32 + nt * 8 + 2 * tg;
            float v0 = c[mt][nt][0], v1 = c[mt][nt][1];
            float v2 = c[mt][nt][2], v3 = c[mt][nt][3];
            if (rope) {
                int p = (col & 127) >> 1;
                int s0 = row & (SEQ - 1);
                int s1 = (row + 8) & (SEQ - 1);
                float c0 = fc[s0 * 64 + p], n0v = fs[s0 * 64 + p];
                float c1 = fc[s1 * 64 + p], n1v = fs[s1 * 64 + p];
                float t0 = v0 * c0 - v1 * n0v, t1 = v0 * n0v + v1 * c0;
                float t2 = v2 * c1 - v3 * n1v, t3 = v2 * n1v + v3 * c1;
                v0 = t0; v1 = t1; v2 = t2; v3 = t3;
            }
            if constexpr (sizeof(CT) == 2) {
                *(__half2*)&C[(size_t)row * N + col] = __floats2half2_rn(v0, v1);
                *(__half2*)&C[(size_t)(row + 8) * N + col] = __floats2half2_rn(v2, v3);
            } else {
                *(float2*)&C[(size_t)row * N + col] = make_float2(v0, v1);
                *(float2*)&C[(size_t)(row + 8) * N + col] = make_float2(v2, v3);
            }
        }
    }
}

// ================= flash attention (causal), fp16 mma.sync =================
// BM=128 q, BN=128 kv. 8 warps, each owns 16 q rows x full 128 kv. P in regs.
// K and V in natural [seq][hd] layout (V B-frags via ldmatrix.trans).
// K/V tiles double-buffered (170KB smem); Q loaded once. One batch per launch.
#define QSTRH 136                       // 128 + 8 pad
#define FQ_H (128*QSTRH)
#define FKV_H (128*QSTRH)
#define FLASH_SMEM ((FQ_H + 4*FKV_H) * 2)   // 174080 B

__global__ __launch_bounds__(256, 1)
void flash_f16(const __half* __restrict__ Q, const __half* __restrict__ K,
               const __half* __restrict__ V, __half* __restrict__ O, int b)
{
    extern __shared__ __half smh[];
    __half* Qs = smh;
    __half* Ks = Qs + FQ_H;              // 2 buffers
    __half* Vs = Ks + 2 * FKV_H;         // 2 buffers

    const int tid = threadIdx.x, wid = tid >> 5, lane = tid & 31;
    const int g = lane >> 2, tg = lane & 3;
    const int qt = (int)(gridDim.x - 1) - (int)blockIdx.x;   // heavy tiles first
    const int h = blockIdx.y;
    const int row0 = b * SEQ + qt * 128;
    const float scale = 0.08838834764831845f;
    const int lrA = lane & 15, lcA = (lane >> 4) << 3;
    const int lrB4 = (lane & 7) | ((lane >> 4) << 3);
    const int lcB4 = ((lane >> 3) & 1) << 3;
    const int lrV = (lane & 7) | ((lane >> 3) & 1) << 3;
    const int lcV = (lane >> 4) << 3;

    auto issue_tile = [&](int jt) {
        const int kv0 = jt << 7;
        __half* Kb = Ks + (jt & 1) * FKV_H;
        __half* Vb = Vs + (jt & 1) * FKV_H;
#pragma unroll
        for (int i = 0; i < 8; i++) {           // K: 128 rows x 16 granules
            int idx = tid + i * 256;
            int row = idx >> 4, gc = (idx & 15) << 3;
            cpasync16(smem_addr(Kb + row * QSTRH + gc),
                      K + (size_t)(b * SEQ + kv0 + row) * DM + h * HD + gc);
        }
#pragma unroll
        for (int i = 0; i < 8; i++) {           // V: same natural layout
            int idx = tid + i * 256;
            int row = idx >> 4, gc = (idx & 15) << 3;
            cpasync16(smem_addr(Vb + row * QSTRH + gc),
                      V + (size_t)(b * SEQ + kv0 + row) * DM + h * HD + gc);
        }
    };

    // Q tile: 128 rows x 16 granules = 2048
#pragma unroll
    for (int i = 0; i < 8; i++) {
        int idx = tid + i * 256;
        int row = idx >> 4, gc = (idx & 15) << 3;
        cpasync16(smem_addr(Qs + row * QSTRH + gc),
                  Q + (size_t)(row0 + row) * DM + h * HD + gc);
    }
    CP_COMMIT;
    issue_tile(0);
    CP_COMMIT;

    float o[16][4];
#pragma unroll
    for (int nt = 0; nt < 16; nt++)
#pragma unroll
        for (int j = 0; j < 4; j++) o[nt][j] = 0.f;
    float mrun0 = -INFINITY, mrun1 = -INFINITY, l0 = 0.f, l1 = 0.f;

    const int ntiles = qt + 1;
    const int qr0 = qt * 128 + wid * 16 + g;
    const int qr1 = qr0 + 8;

    for (int jt = 0; jt < ntiles; jt++) {
        const int kv0 = jt << 7;
        __syncthreads();                       // all warps done with buffer being refilled
        bool pf = (jt + 1 < ntiles);
        if (pf) issue_tile(jt + 1);
        CP_COMMIT;
        if (pf) { CP_WAIT1; } else { CP_WAIT0; }
        __syncthreads();

        const __half* Kb = Ks + (jt & 1) * FKV_H;
        const __half* Vb = Vs + (jt & 1) * FKV_H;

        // ---- S = Q @ K^T : this warp's 16 q rows x 128 kv
        float sc[16][4];
#pragma unroll
        for (int nt = 0; nt < 16; nt++)
#pragma unroll
            for (int j = 0; j < 4; j++) sc[nt][j] = 0.f;

#pragma unroll
        for (int ks = 0; ks < 8; ks++) {
            const int kk = ks * 16;
            uint32_t a[4];
            ldsm4(a, smem_addr(Qs + (wid * 16 + lrA) * QSTRH + kk + lcA));
#pragma unroll
            for (int nt2 = 0; nt2 < 8; nt2++) {
                uint32_t bf[4];
                ldsm4(bf, smem_addr(Kb + (nt2 * 16 + lrB4) * QSTRH + kk + lcB4));
                mma16(sc[nt2 * 2 + 0], a, bf + 0);
                mma16(sc[nt2 * 2 + 1], a, bf + 2);
            }
        }

        // ---- scale + causal mask (only the diagonal tile needs masking)
        const bool need_mask = (jt == qt);
#pragma unroll
        for (int nt = 0; nt < 16; nt++) {
            int kc = kv0 + nt * 8 + 2 * tg;
#pragma unroll
            for (int j = 0; j < 4; j++) {
                float s = sc[nt][j] * scale;
                if (need_mask) {
                    int qr = (j >= 2) ? qr1 : qr0;
                    if (kc + (j & 1) > qr) s = -1e30f;
                }
                sc[nt][j] = s;
            }
        }

        // ---- in-warp online softmax (rows g and g+8 of this warp's block)
        float mx0 = -INFINITY, mx1 = -INFINITY;
#pragma unroll
        for (int nt = 0; nt < 16; nt++) {
            mx0 = fmaxf(mx0, fmaxf(sc[nt][0], sc[nt][1]));
            mx1 = fmaxf(mx1, fmaxf(sc[nt][2], sc[nt][3]));
        }
        mx0 = fmaxf(mx0, __shfl_xor_sync(0xffffffffu, mx0, 1));
        mx0 = fmaxf(mx0, __shfl_xor_sync(0xffffffffu, mx0, 2));
        mx1 = fmaxf(mx1, __shfl_xor_sync(0xffffffffu, mx1, 1));
        mx1 = fmaxf(mx1, __shfl_xor_sync(0xffffffffu, mx1, 2));
        float mn0 = fmaxf(mrun0, mx0), mn1 = fmaxf(mrun1, mx1);
        float fac0 = __expf(mrun0 - mn0), fac1 = __expf(mrun1 - mn1);
        mrun0 = mn0; mrun1 = mn1;

        float s0 = 0.f, s1 = 0.f;
#pragma unroll
        for (int nt = 0; nt < 16; nt++) {
            sc[nt][0] = __expf(sc[nt][0] - mn0);
            sc[nt][1] = __expf(sc[nt][1] - mn0);
            sc[nt][2] = __expf(sc[nt][2] - mn1);
            sc[nt][3] = __expf(sc[nt][3] - mn1);
            s0 += sc[nt][0] + sc[nt][1];
            s1 += sc[nt][2] + sc[nt][3];
        }
        s0 += __shfl_xor_sync(0xffffffffu, s0, 1);
        s0 += __shfl_xor_sync(0xffffffffu, s0, 2);
        s1 += __shfl_xor_sync(0xffffffffu, s1, 1);
        s1 += __shfl_xor_sync(0xffffffffu, s1, 2);
        l0 = l0 * fac0 + s0;
        l1 = l1 * fac1 + s1;

#pragma unroll
        for (int nt = 0; nt < 16; nt++) {
            o[nt][0] *= fac0; o[nt][1] *= fac0;
            o[nt][2] *= fac1; o[nt][3] *= fac1;
        }

        // ---- O += P @ V ; P packed from sc regs; V B-frags via ldmatrix.trans
#pragma unroll
        for (int kb = 0; kb < 8; kb++) {
            uint32_t a[4];
            a[0] = packh2(sc[2 * kb][0],     sc[2 * kb][1]);
            a[1] = packh2(sc[2 * kb][2],     sc[2 * kb][3]);
            a[2] = packh2(sc[2 * kb + 1][0], sc[2 * kb + 1][1]);
            a[3] = packh2(sc[2 * kb + 1][2], sc[2 * kb + 1][3]);
            const int kk = kb * 16;
#pragma unroll
            for (int nt2 = 0; nt2 < 8; nt2++) {
                uint32_t bf[4];
                ldsm4t(bf, smem_addr(Vb + (kk + lrV) * QSTRH + nt2 * 16 + lcV));
                mma16(o[nt2 * 2 + 0], a, bf + 0);
                mma16(o[nt2 * 2 + 1], a, bf + 2);
            }
        }
    }

    // ---- epilogue
    float inv0 = 1.0f / l0, inv1 = 1.0f / l1;
    int row = row0 + wid * 16 + g;
#pragma unroll
    for (int nt = 0; nt < 16; nt++) {
        int col = h * HD + nt * 8 + 2 * tg;
        *(__half2*)&O[(size_t)row * DM + col] =
            __floats2half2_rn(o[nt][0] * inv0, o[nt][1] * inv0);
        *(__half2*)&O[(size_t)(row + 8) * DM + col] =
            __floats2half2_rn(o[nt][2] * inv1, o[nt][3] * inv1);
    }
}

// ---------------- small kernels ----------------
__global__ __launch_bounds__(256) void cvtx_kernel(const float* __restrict__ x,
                                                   __half* __restrict__ y, int n4)
{
    int i = blockIdx.x * 256 + threadIdx.x;
    if (i >= n4) return;
    float4 v = ((const float4*)x)[i];
    ((__half2*)y)[2 * i]     = __floats2half2_rn(v.x, v.y);
    ((__half2*)y)[2 * i + 1] = __floats2half2_rn(v.z, v.w);
}

// src float: transpose [r,c] -> dst half [c,r]
__global__ __launch_bounds__(256) void trans_cvt(const float* __restrict__ src,
                                                 __half* __restrict__ dst, int R, int C)
{
    __shared__ float t[32][33];
    int c0 = blockIdx.x * 32, r0 = blockIdx.y * 32;
    int tx = threadIdx.x & 31, ty = threadIdx.x >> 5;
#pragma unroll
    for (int i = 0; i < 4; i++)
        t[ty + i * 8][tx] = src[(size_t)(r0 + ty + i * 8) * C + c0 + tx];
    __syncthreads();
#pragma unroll
    for (int i = 0; i < 4; i++)
        dst[(size_t)(c0 + ty + i * 8) * R + r0 + tx] = __float2half_rn(t[tx][ty + i * 8]);
}

__global__ __launch_bounds__(256) void rmsnorm_kernel(__half* __restrict__ x,
                                                      const float* __restrict__ w)
{
    const int row = blockIdx.x;
    __half* p = x + (size_t)row * LORA;
    const int t = threadIdx.x;
    float v0 = __half2float(p[t]), v1 = __half2float(p[t + 256]);
    float ss = v0 * v0 + v1 * v1;
#pragma unroll
    for (int o = 16; o; o >>= 1) ss += __shfl_xor_sync(0xffffffffu, ss, o);
    __shared__ float sred[8];
    if ((t & 31) == 0) sred[t >> 5] = ss;
    __syncthreads();
    float tot = 0.f;
#pragma unroll
    for (int i = 0; i < 8; i++) tot += sred[i];
    float inv = rsqrtf(tot * (1.0f / (float)LORA) + 1e-6f);
    p[t]       = __float2half_rn(v0 * inv * w[t]);
    p[t + 256] = __float2half_rn(v1 * inv * w[t + 256]);
}

// ---------------- launch ----------------
extern "C" void kernel_launch(void* const* d_in, const int* in_sizes, int n_in,
                              void* d_out, int out_size)
{
    const float* x     = (const float*)d_in[0];
    const float* fcos  = (const float*)d_in[1];
    const float* fsin  = (const float*)d_in[2];
    const float* w_kvc = (const float*)d_in[3];
    const float* kvw   = (const float*)d_in[4];
    const float* w_k   = (const float*)d_in[5];
    const float* w_v   = (const float*)d_in[6];
    const float* w_q   = (const float*)d_in[7];
    const float* w_o   = (const float*)d_in[8];
    float* out = (float*)d_out;

    __half *xh, *kvl, *Kb, *Vb, *Qb, *Ab;
    __half *wkvcT, *wkT, *wvT, *wqT, *woT;
    cudaGetSymbolAddress((void**)&xh, g_xh);
    cudaGetSymbolAddress((void**)&kvl, g_kvlat);
    cudaGetSymbolAddress((void**)&Kb, g_k);
    cudaGetSymbolAddress((void**)&Vb, g_v);
    cudaGetSymbolAddress((void**)&Qb, g_q);
    cudaGetSymbolAddress((void**)&Ab, g_attn);
    cudaGetSymbolAddress((void**)&wkvcT, g_wkvcT);
    cudaGetSymbolAddress((void**)&wkT, g_wkT);
    cudaGetSymbolAddress((void**)&wvT, g_wvT);
    cudaGetSymbolAddress((void**)&wqT, g_wqT);
    cudaGetSymbolAddress((void**)&woT, g_woT);

    cudaFuncSetAttribute((void*)gemm_f16<__half>, cudaFuncAttributeMaxDynamicSharedMemorySize, GEMM_SMEM);
    cudaFuncSetAttribute((void*)gemm_f16<float>,  cudaFuncAttributeMaxDynamicSharedMemorySize, GEMM_SMEM);
    cudaFuncSetAttribute((void*)flash_f16, cudaFuncAttributeMaxDynamicSharedMemorySize, FLASH_SMEM);

    // one-time side stream + events (host resources; every call does identical GPU work)
    static cudaStream_t s2 = nullptr;
    static cudaEvent_t ev_x = nullptr, ev_join = nullptr, ev_f0 = nullptr, ev_out0 = nullptr;
    if (s2 == nullptr) {
        cudaStreamCreateWithFlags(&s2, cudaStreamNonBlocking);
        cudaEventCreateWithFlags(&ev_x, cudaEventDisableTiming);
        cudaEventCreateWithFlags(&ev_join, cudaEventDisableTiming);
        cudaEventCreateWithFlags(&ev_f0, cudaEventDisableTiming);
        cudaEventCreateWithFlags(&ev_out0, cudaEventDisableTiming);
    }

    // ---- branch B (s2): w_q transpose (no deps) ----
    trans_cvt<<<dim3(DM / 32, DM / 32), 256, 0, s2>>>(w_q, wqT, DM, DM);

    // ---- main: x -> fp16, then signal s2 ----
    cvtx_kernel<<<(ROWS * DM / 4 + 255) / 256, 256>>>(x, xh, ROWS * DM / 4);
    cudaEventRecord(ev_x, 0);
    cudaStreamWaitEvent(s2, ev_x, 0);

    // ---- branch B (s2): q = rope(x @ w_q), then w_o transpose ----
    gemm_f16<__half><<<dim3(DM / 128, ROWS / 128), 256, GEMM_SMEM, s2>>>(
        xh, wqT, Qb, ROWS, DM, DM, fcos, fsin, nullptr, nullptr, 0);
    trans_cvt<<<dim3(DM / 32, DM / 32), 256, 0, s2>>>(w_o, woT, DM, DM);
    cudaEventRecord(ev_join, s2);

    // ---- branch A (main): kv chain ----
    trans_cvt<<<dim3(LORA / 32, DM / 32), 256>>>(w_kvc, wkvcT, DM, LORA);
    gemm_f16<__half><<<dim3(LORA / 128, ROWS / 128), 256, GEMM_SMEM>>>(
        xh, wkvcT, kvl, ROWS, LORA, DM, nullptr, nullptr, nullptr, nullptr, 0);
    rmsnorm_kernel<<<ROWS, 256>>>(kvl, kvw);
    trans_cvt<<<dim3(DM / 32, LORA / 32), 256>>>(w_k, wkT, LORA, DM);
    trans_cvt<<<dim3(DM / 32, LORA / 32), 256>>>(w_v, wvT, LORA, DM);
    // merged k-up (rope) + v-up (no rope): one 1024-CTA launch
    gemm_f16<__half><<<dim3(2 * (DM / 128), ROWS / 128), 256, GEMM_SMEM>>>(
        kvl, wkT, Kb, ROWS, DM, LORA, fcos, fsin, wvT, Vb, DM / 128);

    // ---- join, then flash (batch-split) with out-GEMM overlap ----
    cudaStreamWaitEvent(0, ev_join, 0);
    // flash batch 0
    flash_f16<<<dim3(SEQ / 128, NH, 1), 256, FLASH_SMEM>>>(Qb, Kb, Vb, Ab, 0);
    cudaEventRecord(ev_f0, 0);
    // flash batch 1 (main) overlaps out-GEMM of batch-0 rows (s2)
    flash_f16<<<dim3(SEQ / 128, NH, 1), 256, FLASH_SMEM>>>(Qb, Kb, Vb, Ab, 1);
    cudaStreamWaitEvent(s2, ev_f0, 0);
    gemm_f16<float><<<dim3(DM / 128, SEQ / 128), 256, GEMM_SMEM, s2>>>(
        Ab, woT, out, SEQ, DM, DM, nullptr, nullptr, nullptr, nullptr, 0);
    cudaEventRecord(ev_out0, s2);
    // out-GEMM for batch-1 rows on main
    gemm_f16<float><<<dim3(DM / 128, SEQ / 128), 256, GEMM_SMEM>>>(
        Ab + (size_t)SEQ * DM, woT, out + (size_t)SEQ * DM, SEQ, DM, DM,
        nullptr, nullptr, nullptr, nullptr, 0);
    // join s2 back into main before capture ends
    cudaStreamWaitEvent(0, ev_out0, 0);
}